// round 10
// baseline (speedup 1.0000x reference)
#include <cuda_runtime.h>
#include <cuda_fp16.h>
#include <cstdint>
#include <math.h>

// Problem constants
#define B_   16
#define Q_   300
#define S_   8400
#define DM   256
#define NH   8
#define HD   32
#define LP_  12
#define BQ   (B_*Q_)          // 4800
#define MVAL (B_*S_)          // 134400

// Scratch (static device globals — no allocation)
__device__ __half g_value_h[(size_t)MVAL * DM];  // [B,S,256] fp16 (68.8 MB)
__device__ float  g_oa[(size_t)BQ * 288];        // offsets(192)+attn logits(96)
__device__ float  g_msda[(size_t)BQ * DM];       // sampled output fp32
__device__ __half g_wv_h[DM * DM];               // w_value fp16
__device__ __half g_wo_h[DM * DM];               // w_out fp16
__device__ __half g_woa_hi[320 * DM];            // fused off+attn W, fp16 hi
__device__ __half g_woa_lo[320 * DM];            // fused off+attn W, fp16 lo
__device__ float  g_boa[320];                    // fused bias

// ===========================================================================
// weight prep kernels (tiny, one-time per launch)
// ===========================================================================
__global__ __launch_bounds__(256) void f32_to_f16(
    const float* __restrict__ src, __half* __restrict__ dst, size_t n)
{
    size_t stride = (size_t)gridDim.x * blockDim.x * 8;
    for (size_t i = ((size_t)blockIdx.x * blockDim.x + threadIdx.x) * 8;
         i < n; i += stride) {
        float4 a = *(const float4*)(src + i);
        float4 b = *(const float4*)(src + i + 4);
        __half2 h0 = __floats2half2_rn(a.x, a.y);
        __half2 h1 = __floats2half2_rn(a.z, a.w);
        __half2 h2 = __floats2half2_rn(b.x, b.y);
        __half2 h3 = __floats2half2_rn(b.z, b.w);
        uint4 o;
        o.x = *(uint32_t*)&h0; o.y = *(uint32_t*)&h1;
        o.z = *(uint32_t*)&h2; o.w = *(uint32_t*)&h3;
        *(uint4*)(dst + i) = o;
    }
}

// Pack Woff(192)+Wattn(96)+zeros(32) rows into hi/lo fp16 split + bias.
__global__ __launch_bounds__(256) void pack_split_woa(
    const float* __restrict__ Woff,  const float* __restrict__ boff,
    const float* __restrict__ Wattn, const float* __restrict__ battn,
    __half* __restrict__ Whi, __half* __restrict__ Wlo,
    float* __restrict__ bdst)
{
    const int r = blockIdx.x;      // 0..319
    const int k = threadIdx.x;     // 0..255
    float v = 0.f;
    if (r < 192)      v = Woff[r * DM + k];
    else if (r < 288) v = Wattn[(r - 192) * DM + k];
    __half h = __float2half_rn(v);
    Whi[r * DM + k] = h;
    Wlo[r * DM + k] = __float2half_rn(v - __half2float(h));
    if (k == 0) bdst[r] = (r < 192) ? boff[r] : (r < 288 ? battn[r - 192] : 0.f);
}

// ===========================================================================
// helpers
// ===========================================================================
__device__ __forceinline__ void mma_m16n8k16_f16(
    float c[4], const uint32_t a[4], const uint32_t b[2])
{
    asm volatile(
        "mma.sync.aligned.m16n8k16.row.col.f32.f16.f16.f32 "
        "{%0,%1,%2,%3}, {%4,%5,%6,%7}, {%8,%9}, {%0,%1,%2,%3};"
        : "+f"(c[0]), "+f"(c[1]), "+f"(c[2]), "+f"(c[3])
        : "r"(a[0]), "r"(a[1]), "r"(a[2]), "r"(a[3]),
          "r"(b[0]), "r"(b[1]));
}
__device__ __forceinline__ uint32_t pack_f16x2(float lo, float hi) {
    uint32_t r;
    asm("cvt.rn.f16x2.f32 %0, %1, %2;" : "=r"(r) : "f"(hi), "f"(lo));
    return r;
}
__device__ __forceinline__ void cp_async16(uint32_t dst, const void* src, bool valid) {
    int sz = valid ? 16 : 0;
    asm volatile("cp.async.cg.shared.global [%0], [%1], 16, %2;"
                 :: "r"(dst), "l"(src), "r"(sz));
}
#define CP_COMMIT()  asm volatile("cp.async.commit_group;" ::: "memory")
#define CP_WAIT(N)   asm volatile("cp.async.wait_group %0;" :: "n"(N) : "memory")

// ===========================================================================
// Staged-f16 GEMM: C[M,256] = f16(A_f32[M,256]) @ W_f16[256,256]^T + bias
// CTA tile 64x256, 8 warps (2m x 4n), warp tile 32x64, 2 CTAs/SM.
// A: LDG fp32 -> cvt f16 -> STS (distance-1 prefetch; all-f16 fragments,
//    no cvt in hot loop, halved A crossbar phases).
// B: cp.async f16, depth-3, 4 stages.
// Row pad = 20 words for A(f16) and B(f16): fragment LDS32s cover all 32
// banks; STS.128 banks {0,20,8,28,16,4,24,12}+q conflict-free.
// ===========================================================================
#define GK      256
#define SBK     32
#define SNCH    (GK / SBK)      // 8 chunks
#define SPAD    20              // words per row (16 data + 4 pad)
#define SAW     (64 * SPAD)     // 1280 words (A f16 tile)
#define SBW     (256 * SPAD)    // 5120 words (B f16 tile)
#define SSTAGEW (SAW + SBW)     // 6400 words = 25600 B
#define SNSTAGE 4

template <bool HALF_OUT>
__global__ __launch_bounds__(256, 2) void gemm_staged(
    const float* __restrict__ A, const __half* __restrict__ W,
    const float* __restrict__ bias, void* __restrict__ Cv, int M)
{
    extern __shared__ uint32_t sm[];

    const int tid  = threadIdx.x;
    const int wid  = tid >> 5;
    const int lane = tid & 31;
    const int grp  = lane >> 2;
    const int tig  = lane & 3;

    const int wm = (wid & 1) * 32;
    const int wn = (wid >> 1) * 64;
    const int m0 = blockIdx.x * 64;

    const uint32_t smem_u32 = (uint32_t)__cvta_generic_to_shared(sm);

    float acc[2][8][4];
#pragma unroll
    for (int i = 0; i < 2; i++)
#pragma unroll
        for (int j = 0; j < 8; j++)
#pragma unroll
            for (int l = 0; l < 4; l++) acc[i][j][l] = 0.f;

    // --- A staging: each thread owns (row = tid&63, q = tid>>6) ---
    const int arow = tid & 63;
    const int aq   = tid >> 6;
    uint32_t ra[4];

    auto lda = [&](int c) {
        const int mg = m0 + arow;
        float4 v0 = make_float4(0.f, 0.f, 0.f, 0.f), v1 = v0;
        if (mg < M) {
            const float* src = A + (size_t)mg * GK + c * SBK + aq * 8;
            v0 = *(const float4*)src;
            v1 = *(const float4*)(src + 4);
        }
        ra[0] = pack_f16x2(v0.x, v0.y);
        ra[1] = pack_f16x2(v0.z, v0.w);
        ra[2] = pack_f16x2(v1.x, v1.y);
        ra[3] = pack_f16x2(v1.z, v1.w);
    };
    auto stsa = [&](int s) {
        uint32_t* dst = sm + s * SSTAGEW + arow * SPAD + aq * 4;
        *(uint4*)dst = make_uint4(ra[0], ra[1], ra[2], ra[3]);
    };
    // --- B via cp.async ---
    auto issueB = [&](int c, int s) {
        const uint32_t bbase = smem_u32 + (uint32_t)(s * SSTAGEW + SAW) * 4u;
        const int k0 = c * SBK;
#pragma unroll
        for (int it = 0; it < 4; ++it) {
            int idx = tid + it * 256;
            int row = idx >> 2, col = idx & 3;
            const __half* src = W + (size_t)row * GK + k0 + col * 8;
            cp_async16(bbase + (uint32_t)(row * SPAD + col * 4) * 4u, src, true);
        }
        CP_COMMIT();
    };

    // prologue
    lda(0);
    issueB(0, 0); issueB(1, 1); issueB(2, 2);
    stsa(0);
    lda(1);

    for (int c = 0; c < SNCH; ++c) {
        CP_WAIT(2);           // B chunk c resident
        __syncthreads();      // A STS(c)+B(c) visible; chunk c-1 reads done

        if (c + 3 < SNCH) issueB(c + 3, (c + 3) & 3);   // stage (c-1)&3: freed by barrier above
        else CP_COMMIT();
        if (c + 1 < SNCH) stsa((c + 1) & 3);            // stage last read at chunk c-3
        if (c + 2 < SNCH) lda(c + 2);

        const uint32_t* sA = sm + (c & 3) * SSTAGEW;
        const uint32_t* sB = sA + SAW;

#pragma unroll
        for (int kk = 0; kk < 2; ++kk) {
            const int kb = kk * 8 + tig;
            uint32_t af[2][4];
#pragma unroll
            for (int mf = 0; mf < 2; ++mf) {
                const int m = wm + mf * 16 + grp;
                af[mf][0] = sA[m * SPAD + kb];
                af[mf][1] = sA[(m + 8) * SPAD + kb];
                af[mf][2] = sA[m * SPAD + kb + 4];
                af[mf][3] = sA[(m + 8) * SPAD + kb + 4];
            }
#pragma unroll
            for (int nf = 0; nf < 8; ++nf) {
                const int n = wn + nf * 8 + grp;
                uint32_t bf[2];
                bf[0] = sB[n * SPAD + kb];
                bf[1] = sB[n * SPAD + kb + 4];
#pragma unroll
                for (int mf = 0; mf < 2; ++mf)
                    mma_m16n8k16_f16(acc[mf][nf], af[mf], bf);
            }
        }
    }

    // ---- epilogue ----
#pragma unroll
    for (int mf = 0; mf < 2; ++mf) {
        const int mlo = m0 + wm + mf * 16 + grp;
#pragma unroll
        for (int nf = 0; nf < 8; ++nf) {
            const int col = wn + nf * 8 + 2 * tig;
            const float bx = __ldg(&bias[col]);
            const float by = __ldg(&bias[col + 1]);
            if (HALF_OUT) {
                __half* C = (__half*)Cv;
                if (mlo < M) {
                    uint32_t p = pack_f16x2(acc[mf][nf][0] + bx, acc[mf][nf][1] + by);
                    *(uint32_t*)(C + (size_t)mlo * DM + col) = p;
                }
                if (mlo + 8 < M) {
                    uint32_t p = pack_f16x2(acc[mf][nf][2] + bx, acc[mf][nf][3] + by);
                    *(uint32_t*)(C + (size_t)(mlo + 8) * DM + col) = p;
                }
            } else {
                float* C = (float*)Cv;
                if (mlo < M) {
                    float2 v = make_float2(acc[mf][nf][0] + bx, acc[mf][nf][1] + by);
                    *(float2*)(C + (size_t)mlo * DM + col) = v;
                }
                if (mlo + 8 < M) {
                    float2 v = make_float2(acc[mf][nf][2] + bx, acc[mf][nf][3] + by);
                    *(float2*)(C + (size_t)(mlo + 8) * DM + col) = v;
                }
            }
        }
    }
}

// ===========================================================================
// Split-fp16 TC GEMM for offsets+attn: C[4800,288] = hs @ Woa^T + b
// 3-term compensated fp16: C = Ah*Bh + Ah*Bl + Al*Bh (error ~2e-7).
// ===========================================================================
#define PADA    40
#define PADB    20
#define CBK     32
#define CNCH    8
#define DAW     (64 * PADA)          // 2560 words
#define DBW     (320 * PADB)         // 6400 words
#define DSTAGEW (DAW + 2 * DBW)      // 15360 words
#define DNSTAGE 3

__global__ __launch_bounds__(256) void gemm_dual_tc(
    const float* __restrict__ A,
    const __half* __restrict__ Whi, const __half* __restrict__ Wlo,
    const float* __restrict__ bias, float* __restrict__ C, int M)
{
    extern __shared__ uint32_t sm[];

    const int tid  = threadIdx.x;
    const int wid  = tid >> 5;
    const int lane = tid & 31;
    const int grp  = lane >> 2;
    const int tig  = lane & 3;

    const int wm = (wid & 1) * 32;
    const int wn = (wid >> 1) * 80;
    const int m0 = blockIdx.x * 64;

    const uint32_t smem_u32 = (uint32_t)__cvta_generic_to_shared(sm);

    float acc[2][10][4];
#pragma unroll
    for (int i = 0; i < 2; i++)
#pragma unroll
        for (int j = 0; j < 10; j++)
#pragma unroll
            for (int l = 0; l < 4; l++) acc[i][j][l] = 0.f;

    auto issue = [&](int c, int s) {
        const uint32_t abase  = smem_u32 + (uint32_t)(s * DSTAGEW) * 4u;
        const uint32_t bhbase = abase + (uint32_t)DAW * 4u;
        const uint32_t blbase = bhbase + (uint32_t)DBW * 4u;
        const int k0 = c * CBK;
#pragma unroll
        for (int it = 0; it < 2; ++it) {
            int idx = tid + it * 256;
            int row = idx >> 3, col = idx & 7;
            bool v = (m0 + row) < M;
            const float* src = A + (size_t)(m0 + row) * GK + k0 + col * 4;
            cp_async16(abase + (uint32_t)(row * PADA + col * 4) * 4u, src, v);
        }
#pragma unroll
        for (int it = 0; it < 5; ++it) {
            int idx = tid + it * 256;
            int row = idx >> 2, col = idx & 3;
            const __half* srch = Whi + (size_t)row * GK + k0 + col * 8;
            cp_async16(bhbase + (uint32_t)(row * PADB + col * 4) * 4u, srch, true);
        }
#pragma unroll
        for (int it = 0; it < 5; ++it) {
            int idx = tid + it * 256;
            int row = idx >> 2, col = idx & 3;
            const __half* srcl = Wlo + (size_t)row * GK + k0 + col * 8;
            cp_async16(blbase + (uint32_t)(row * PADB + col * 4) * 4u, srcl, true);
        }
        CP_COMMIT();
    };

    issue(0, 0);
    issue(1, 1);

    for (int c = 0; c < CNCH; ++c) {
        CP_WAIT(1);
        __syncthreads();

        if (c + 2 < CNCH) issue(c + 2, (c + 2) % DNSTAGE);
        else CP_COMMIT();

        const uint32_t* sAw = sm + (c % DNSTAGE) * DSTAGEW;
        const float*    sA  = (const float*)sAw;
        const uint32_t* sBh = sAw + DAW;
        const uint32_t* sBl = sBh + DBW;

#pragma unroll
        for (int kk = 0; kk < 2; ++kk) {
            const int ka = kk * 16 + 2 * tig;
            const int kb = kk * 8 + tig;
            uint32_t ah[2][4], al[2][4];
#pragma unroll
            for (int mf = 0; mf < 2; ++mf) {
                const int m = wm + mf * 16 + grp;
                float2 a0 = *(const float2*)(sA + m * PADA + ka);
                float2 a1 = *(const float2*)(sA + (m + 8) * PADA + ka);
                float2 a2 = *(const float2*)(sA + m * PADA + ka + 8);
                float2 a3 = *(const float2*)(sA + (m + 8) * PADA + ka + 8);
#pragma unroll
                for (int q = 0; q < 4; ++q) {
                    float2 av = (q == 0) ? a0 : (q == 1) ? a1 : (q == 2) ? a2 : a3;
                    uint32_t hi = pack_f16x2(av.x, av.y);
                    float2 hf = __half22float2(*(__half2*)&hi);
                    ah[mf][q] = hi;
                    al[mf][q] = pack_f16x2(av.x - hf.x, av.y - hf.y);
                }
            }
#pragma unroll
            for (int nf = 0; nf < 10; ++nf) {
                const int n = wn + nf * 8 + grp;
                uint32_t bh[2], bl[2];
                bh[0] = sBh[n * PADB + kb];
                bh[1] = sBh[n * PADB + kb + 4];
                bl[0] = sBl[n * PADB + kb];
                bl[1] = sBl[n * PADB + kb + 4];
#pragma unroll
                for (int mf = 0; mf < 2; ++mf) {
                    mma_m16n8k16_f16(acc[mf][nf], ah[mf], bh);
                    mma_m16n8k16_f16(acc[mf][nf], ah[mf], bl);
                    mma_m16n8k16_f16(acc[mf][nf], al[mf], bh);
                }
            }
        }
    }

#pragma unroll
    for (int mf = 0; mf < 2; ++mf) {
        const int mlo = m0 + wm + mf * 16 + grp;
#pragma unroll
        for (int nf = 0; nf < 10; ++nf) {
            const int col = wn + nf * 8 + 2 * tig;
            if (col >= 288) continue;
            const float bx = __ldg(&bias[col]);
            const float by = __ldg(&bias[col + 1]);
            if (mlo < M) {
                float2 v = make_float2(acc[mf][nf][0] + bx, acc[mf][nf][1] + by);
                *(float2*)(C + (size_t)mlo * 288 + col) = v;
            }
            if (mlo + 8 < M) {
                float2 v = make_float2(acc[mf][nf][2] + bx, acc[mf][nf][3] + by);
                *(float2*)(C + (size_t)(mlo + 8) * 288 + col) = v;
            }
        }
    }
}

// ---------------------------------------------------------------------------
// Sampling kernel: block per (b,q). value is fp16 (L2-resident at 68.8 MB).
// ---------------------------------------------------------------------------
__global__ __launch_bounds__(256) void msda_sample2(
    const __half* __restrict__ value,
    const float* __restrict__ oa,
    const float* __restrict__ refp,
    float* __restrict__ out)
{
    __shared__ float  s_logit[96];
    __shared__ float2 s_mxinv[8];
    __shared__ int4   s_ofs[96];
    __shared__ float4 s_wts[96];

    const int bq = blockIdx.x;
    const int b  = bq / Q_;
    const int t  = threadIdx.x;

    if (t < 96) s_logit[t] = oa[(size_t)bq * 288 + 192 + t];
    __syncthreads();

    if (t < 8) {
        float mx = -1e30f;
#pragma unroll
        for (int p = 0; p < LP_; p++) mx = fmaxf(mx, s_logit[t * LP_ + p]);
        float s = 0.f;
#pragma unroll
        for (int p = 0; p < LP_; p++) s += __expf(s_logit[t * LP_ + p] - mx);
        s_mxinv[t] = make_float2(mx, 1.f / s);
    }
    __syncthreads();

    if (t < 96) {
        const int h = t / LP_;
        const int p = t - h * LP_;
        const float2 mi = s_mxinv[h];
        const float aw = __expf(s_logit[t] - mi.x) * mi.y;

        const float rx = refp[bq * 4 + 0];
        const float ry = refp[bq * 4 + 1];
        const float rw = refp[bq * 4 + 2];
        const float rh = refp[bq * 4 + 3];

        const float ox = oa[(size_t)bq * 288 + h * 24 + 2 * p + 0];
        const float oy = oa[(size_t)bq * 288 + h * 24 + 2 * p + 1];

        const int lvl   = p >> 2;
        const int Wl    = (lvl == 0) ? 80 : (lvl == 1) ? 40 : 20;
        const int start = (lvl == 0) ? 0 : (lvl == 1) ? 6400 : 8000;

        const float gx = (rx + ox * 0.125f * rw) * (float)Wl - 0.5f;
        const float gy = (ry + oy * 0.125f * rh) * (float)Wl - 0.5f;

        const float x0f = floorf(gx), y0f = floorf(gy);
        const int x0 = (int)x0f, y0 = (int)y0f;
        const int x1 = x0 + 1,  y1 = y0 + 1;
        const float wx1 = gx - x0f, wx0 = 1.f - wx1;
        const float wy1 = gy - y0f, wy0 = 1.f - wy1;

        const bool xv0 = (x0 >= 0) & (x0 < Wl);
        const bool xv1 = (x1 >= 0) & (x1 < Wl);
        const bool yv0 = (y0 >= 0) & (y0 < Wl);
        const bool yv1 = (y1 >= 0) & (y1 < Wl);

        const int x0c = min(max(x0, 0), Wl - 1);
        const int x1c = min(max(x1, 0), Wl - 1);
        const int y0c = min(max(y0, 0), Wl - 1);
        const int y1c = min(max(y1, 0), Wl - 1);

        const int rb = b * S_ + start;
        const int r0 = rb + y0c * Wl;
        const int r1 = rb + y1c * Wl;
        const int hb = h * HD;

        int4 o;
        o.x = (r0 + x0c) * DM + hb;
        o.y = (r0 + x1c) * DM + hb;
        o.z = (r1 + x0c) * DM + hb;
        o.w = (r1 + x1c) * DM + hb;

        float4 w;
        w.x = aw * wx0 * wy0 * (float)(xv0 & yv0);
        w.y = aw * wx1 * wy0 * (float)(xv1 & yv0);
        w.z = aw * wx0 * wy1 * (float)(xv0 & yv1);
        w.w = aw * wx1 * wy1 * (float)(xv1 & yv1);

        s_ofs[t] = o;
        s_wts[t] = w;
    }
    __syncthreads();

    const int h    = t >> 5;
    const int lane = t & 31;
    float acc = 0.f;
#pragma unroll
    for (int p = 0; p < LP_; p++) {
        const int4   o = s_ofs[h * LP_ + p];
        const float4 w = s_wts[h * LP_ + p];
        acc += w.x * __half2float(__ldg(&value[o.x + lane]));
        acc += w.y * __half2float(__ldg(&value[o.y + lane]));
        acc += w.z * __half2float(__ldg(&value[o.z + lane]));
        acc += w.w * __half2float(__ldg(&value[o.w + lane]));
    }
    out[(size_t)bq * DM + h * HD + lane] = acc;
}

// ---------------------------------------------------------------------------
extern "C" void kernel_launch(void* const* d_in, const int* in_sizes, int n_in,
                              void* d_out, int out_size)
{
    const float* hs      = (const float*)d_in[0];
    const float* ehs     = (const float*)d_in[1];
    const float* refp    = (const float*)d_in[2];
    const float* w_value = (const float*)d_in[3];
    const float* b_value = (const float*)d_in[4];
    const float* w_off   = (const float*)d_in[5];
    const float* b_off   = (const float*)d_in[6];
    const float* w_attn  = (const float*)d_in[7];
    const float* b_attn  = (const float*)d_in[8];
    const float* w_out   = (const float*)d_in[9];
    const float* b_out   = (const float*)d_in[10];
    float* out = (float*)d_out;

    float  *poa, *pmsda, *pboa;
    __half *pvalh, *pwv, *pwo, *pwhi, *pwlo;
    cudaGetSymbolAddress((void**)&pvalh, g_value_h);
    cudaGetSymbolAddress((void**)&poa,   g_oa);
    cudaGetSymbolAddress((void**)&pmsda, g_msda);
    cudaGetSymbolAddress((void**)&pwv,   g_wv_h);
    cudaGetSymbolAddress((void**)&pwo,   g_wo_h);
    cudaGetSymbolAddress((void**)&pwhi,  g_woa_hi);
    cudaGetSymbolAddress((void**)&pwlo,  g_woa_lo);
    cudaGetSymbolAddress((void**)&pboa,  g_boa);

    const int smem_val  = SNSTAGE * SSTAGEW * 4;   // 102400 B
    const int smem_dual = DNSTAGE * DSTAGEW * 4;   // 184320 B
    cudaFuncSetAttribute(gemm_staged<true>,
                         cudaFuncAttributeMaxDynamicSharedMemorySize, smem_val);
    cudaFuncSetAttribute(gemm_staged<false>,
                         cudaFuncAttributeMaxDynamicSharedMemorySize, smem_val);
    cudaFuncSetAttribute(gemm_dual_tc,
                         cudaFuncAttributeMaxDynamicSharedMemorySize, smem_dual);

    // 0. weight prep (tiny)
    f32_to_f16<<<64, 256>>>(w_value, pwv, (size_t)DM * DM);
    f32_to_f16<<<64, 256>>>(w_out, pwo, (size_t)DM * DM);
    pack_split_woa<<<320, 256>>>(w_off, b_off, w_attn, b_attn, pwhi, pwlo, pboa);

    // 1. value = ehs @ w_value^T + b_value  (fp16 output)
    gemm_staged<true><<<MVAL / 64, 256, smem_val>>>(ehs, pwv, b_value,
                                                    (void*)pvalh, MVAL);
    // 2. offsets+attn projection (split-fp16 TC)
    gemm_dual_tc<<<BQ / 64, 256, smem_dual>>>(hs, pwhi, pwlo, pboa, poa, BQ);
    // 3. softmax + bilinear sampling + weighted sum (fp16 value reads)
    msda_sample2<<<BQ, 256>>>(pvalh, poa, refp, pmsda);
    // 4. out = msda @ w_out^T + b_out  (fp32 output)
    gemm_staged<false><<<BQ / 64, 256, smem_val>>>(pmsda, pwo, b_out,
                                                   (void*)out, BQ);
}

// round 11
// speedup vs baseline: 1.3586x; 1.3586x over previous
#include <cuda_runtime.h>
#include <cuda_fp16.h>
#include <cstdint>
#include <math.h>

// Problem constants
#define B_   16
#define Q_   300
#define S_   8400
#define DM   256
#define NH   8
#define HD   32
#define LP_  12
#define BQ   (B_*Q_)          // 4800
#define MVAL (B_*S_)          // 134400

// Scratch (static device globals — no allocation)
__device__ __half g_value_h[(size_t)MVAL * DM];  // [B,S,256] fp16 (68.8 MB)
__device__ float  g_oa[(size_t)BQ * 288];        // offsets(192)+attn logits(96)
__device__ float  g_msda[(size_t)BQ * DM];       // sampled output fp32
__device__ __half g_wv_h[DM * DM];               // w_value fp16
__device__ __half g_wo_h[DM * DM];               // w_out fp16
__device__ __half g_woa_hi[320 * DM];            // fused off+attn W, fp16 hi
__device__ __half g_woa_lo[320 * DM];            // fused off+attn W, fp16 lo
__device__ float  g_boa[320];                    // fused bias

// ===========================================================================
// One-shot weight prep: blocks 0..255 wv, 256..511 wo, 512..831 woa split
// ===========================================================================
__global__ __launch_bounds__(256) void prep_weights(
    const float* __restrict__ Wv, const float* __restrict__ Wo,
    const float* __restrict__ Woff,  const float* __restrict__ boff,
    const float* __restrict__ Wattn, const float* __restrict__ battn,
    __half* __restrict__ wv_h, __half* __restrict__ wo_h,
    __half* __restrict__ whi, __half* __restrict__ wlo,
    float* __restrict__ boa)
{
    const int r = blockIdx.x;
    const int k = threadIdx.x;
    if (r < 256) {
        wv_h[r * DM + k] = __float2half_rn(Wv[r * DM + k]);
    } else if (r < 512) {
        int rr = r - 256;
        wo_h[rr * DM + k] = __float2half_rn(Wo[rr * DM + k]);
    } else {
        int rr = r - 512;           // 0..319
        float v = 0.f;
        if (rr < 192)      v = Woff[rr * DM + k];
        else if (rr < 288) v = Wattn[(rr - 192) * DM + k];
        __half h = __float2half_rn(v);
        whi[rr * DM + k] = h;
        wlo[rr * DM + k] = __float2half_rn(v - __half2float(h));
        if (k == 0) boa[rr] = (rr < 192) ? boff[rr]
                                         : (rr < 288 ? battn[rr - 192] : 0.f);
    }
}

// ===========================================================================
// helpers
// ===========================================================================
__device__ __forceinline__ void mma_m16n8k16_f16(
    float c[4], const uint32_t a[4], const uint32_t b[2])
{
    asm volatile(
        "mma.sync.aligned.m16n8k16.row.col.f32.f16.f16.f32 "
        "{%0,%1,%2,%3}, {%4,%5,%6,%7}, {%8,%9}, {%0,%1,%2,%3};"
        : "+f"(c[0]), "+f"(c[1]), "+f"(c[2]), "+f"(c[3])
        : "r"(a[0]), "r"(a[1]), "r"(a[2]), "r"(a[3]),
          "r"(b[0]), "r"(b[1]));
}
__device__ __forceinline__ uint32_t pack_f16x2(float lo, float hi) {
    uint32_t r;
    asm("cvt.rn.f16x2.f32 %0, %1, %2;" : "=r"(r) : "f"(hi), "f"(lo));
    return r;
}
__device__ __forceinline__ void cp_async16(uint32_t dst, const void* src, bool valid) {
    int sz = valid ? 16 : 0;
    asm volatile("cp.async.cg.shared.global [%0], [%1], 16, %2;"
                 :: "r"(dst), "l"(src), "r"(sz));
}
#define CP_COMMIT()  asm volatile("cp.async.commit_group;" ::: "memory")
#define CP_WAIT(N)   asm volatile("cp.async.wait_group %0;" :: "n"(N) : "memory")

#define GK   256
#define CBK  32

// ===========================================================================
// BIG value GEMM: C[M,256] = f16(A_f32) @ W_f16^T + bias  -> fp16 out
// CTA tile 128x256, 8 warps (4m x 2n), warp tile 32x128, 1 CTA/SM.
// BK=32, 4-stage cp.async (wait 2). A fp32 in SMEM (PADA=40, conflict-free
// LDS64 fragments), cvt to f16 at fragment load. B f16 (PADB=20).
// ===========================================================================
#define VPADA   40
#define VPADB   20
#define VAW     (128 * VPADA)    // 5120 words
#define VBW     (256 * VPADB)    // 5120 words
#define VSTAGEW (VAW + VBW)      // 10240 words = 40960 B
#define VNSTAGE 4
#define VNCH    (GK / CBK)       // 8

__global__ __launch_bounds__(256, 1) void gemm_value_big(
    const float* __restrict__ A, const __half* __restrict__ W,
    const float* __restrict__ bias, __half* __restrict__ C, int M)
{
    extern __shared__ uint32_t sm[];

    const int tid  = threadIdx.x;
    const int wid  = tid >> 5;
    const int lane = tid & 31;
    const int grp  = lane >> 2;
    const int tig  = lane & 3;

    const int wm = (wid & 3) * 32;     // 4 m groups
    const int wn = (wid >> 2) * 128;   // 2 n groups
    const int m0 = blockIdx.x * 128;

    const uint32_t smem_u32 = (uint32_t)__cvta_generic_to_shared(sm);

    float acc[2][16][4];
#pragma unroll
    for (int i = 0; i < 2; i++)
#pragma unroll
        for (int j = 0; j < 16; j++)
#pragma unroll
            for (int l = 0; l < 4; l++) acc[i][j][l] = 0.f;

    auto issue = [&](int c, int s) {
        const uint32_t abase = smem_u32 + (uint32_t)(s * VSTAGEW) * 4u;
        const uint32_t bbase = abase + (uint32_t)VAW * 4u;
        const int k0 = c * CBK;
        // A fp32: 128 rows x 8 16B-chunks = 1024 -> 4/thread
#pragma unroll
        for (int it = 0; it < 4; ++it) {
            int idx = tid + it * 256;
            int row = idx >> 3, col = idx & 7;
            bool v = (m0 + row) < M;
            const float* src = A + (size_t)(m0 + row) * GK + k0 + col * 4;
            cp_async16(abase + (uint32_t)(row * VPADA + col * 4) * 4u, src, v);
        }
        // B f16: 256 rows x 4 16B-chunks = 1024 -> 4/thread
#pragma unroll
        for (int it = 0; it < 4; ++it) {
            int idx = tid + it * 256;
            int row = idx >> 2, col = idx & 3;
            const __half* src = W + (size_t)row * GK + k0 + col * 8;
            cp_async16(bbase + (uint32_t)(row * VPADB + col * 4) * 4u, src, true);
        }
        CP_COMMIT();
    };

    issue(0, 0);
    issue(1, 1);
    issue(2, 2);

    for (int c = 0; c < VNCH; ++c) {
        CP_WAIT(2);           // chunk c resident
        __syncthreads();      // chunk c visible; chunk c-1 reads done

        if (c + 3 < VNCH) issue(c + 3, (c + 3) & 3);  // stage (c-1)&3: freed
        else CP_COMMIT();

        const uint32_t* sAw = sm + (c & 3) * VSTAGEW;
        const float*    sA  = (const float*)sAw;
        const uint32_t* sB  = sAw + VAW;

#pragma unroll
        for (int kk = 0; kk < 2; ++kk) {
            const int ka = kk * 16 + 2 * tig;
            const int kb = kk * 8 + tig;
            uint32_t af[2][4];
#pragma unroll
            for (int mf = 0; mf < 2; ++mf) {
                const int m = wm + mf * 16 + grp;
                float2 a0 = *(const float2*)(sA + m * VPADA + ka);
                float2 a1 = *(const float2*)(sA + (m + 8) * VPADA + ka);
                float2 a2 = *(const float2*)(sA + m * VPADA + ka + 8);
                float2 a3 = *(const float2*)(sA + (m + 8) * VPADA + ka + 8);
                af[mf][0] = pack_f16x2(a0.x, a0.y);
                af[mf][1] = pack_f16x2(a1.x, a1.y);
                af[mf][2] = pack_f16x2(a2.x, a2.y);
                af[mf][3] = pack_f16x2(a3.x, a3.y);
            }
#pragma unroll
            for (int nf = 0; nf < 16; ++nf) {
                const int n = wn + nf * 8 + grp;
                uint32_t bf[2];
                bf[0] = sB[n * VPADB + kb];
                bf[1] = sB[n * VPADB + kb + 4];
#pragma unroll
                for (int mf = 0; mf < 2; ++mf)
                    mma_m16n8k16_f16(acc[mf][nf], af[mf], bf);
            }
        }
    }

    // ---- epilogue (fp16 out) ----
#pragma unroll
    for (int mf = 0; mf < 2; ++mf) {
        const int mlo = m0 + wm + mf * 16 + grp;
#pragma unroll
        for (int nf = 0; nf < 16; ++nf) {
            const int col = wn + nf * 8 + 2 * tig;
            const float bx = __ldg(&bias[col]);
            const float by = __ldg(&bias[col + 1]);
            if (mlo < M) {
                uint32_t p = pack_f16x2(acc[mf][nf][0] + bx, acc[mf][nf][1] + by);
                *(uint32_t*)(C + (size_t)mlo * DM + col) = p;
            }
            if (mlo + 8 < M) {
                uint32_t p = pack_f16x2(acc[mf][nf][2] + bx, acc[mf][nf][3] + by);
                *(uint32_t*)(C + (size_t)(mlo + 8) * DM + col) = p;
            }
        }
    }
}

// ===========================================================================
// 64-tile mixed GEMM (out-projection): C fp32 = f16(A_f32) @ W_f16^T + bias
// CTA tile 64x256, 8 warps (2m x 4n), 2 CTAs/SM, 3-stage cp.async.
// ===========================================================================
#define PADA    40
#define PADB    20
#define CNCH    8
#define CAW     (64 * PADA)
#define CBW     (256 * PADB)
#define CSTAGEW (CAW + CBW)
#define CNSTAGE 3

__global__ __launch_bounds__(256, 2) void gemm_small(
    const float* __restrict__ A, const __half* __restrict__ W,
    const float* __restrict__ bias, float* __restrict__ C, int M)
{
    extern __shared__ uint32_t sm[];

    const int tid  = threadIdx.x;
    const int wid  = tid >> 5;
    const int lane = tid & 31;
    const int grp  = lane >> 2;
    const int tig  = lane & 3;

    const int wm = (wid & 1) * 32;
    const int wn = (wid >> 1) * 64;
    const int m0 = blockIdx.x * 64;

    const uint32_t smem_u32 = (uint32_t)__cvta_generic_to_shared(sm);

    float acc[2][8][4];
#pragma unroll
    for (int i = 0; i < 2; i++)
#pragma unroll
        for (int j = 0; j < 8; j++)
#pragma unroll
            for (int l = 0; l < 4; l++) acc[i][j][l] = 0.f;

    auto issue = [&](int c, int s) {
        const uint32_t abase = smem_u32 + (uint32_t)(s * CSTAGEW) * 4u;
        const uint32_t bbase = abase + (uint32_t)CAW * 4u;
        const int k0 = c * CBK;
#pragma unroll
        for (int it = 0; it < 2; ++it) {
            int idx = tid + it * 256;
            int row = idx >> 3, col = idx & 7;
            bool v = (m0 + row) < M;
            const float* src = A + (size_t)(m0 + row) * GK + k0 + col * 4;
            cp_async16(abase + (uint32_t)(row * PADA + col * 4) * 4u, src, v);
        }
#pragma unroll
        for (int it = 0; it < 4; ++it) {
            int idx = tid + it * 256;
            int row = idx >> 2, col = idx & 3;
            const __half* src = W + (size_t)row * GK + k0 + col * 8;
            cp_async16(bbase + (uint32_t)(row * PADB + col * 4) * 4u, src, true);
        }
        CP_COMMIT();
    };

    issue(0, 0);
    issue(1, 1);

    for (int c = 0; c < CNCH; ++c) {
        CP_WAIT(1);
        __syncthreads();

        if (c + 2 < CNCH) issue(c + 2, (c + 2) % CNSTAGE);
        else CP_COMMIT();

        const uint32_t* sAw = sm + (c % CNSTAGE) * CSTAGEW;
        const float*    sA  = (const float*)sAw;
        const uint32_t* sB  = sAw + CAW;

#pragma unroll
        for (int kk = 0; kk < 2; ++kk) {
            const int ka = kk * 16 + 2 * tig;
            const int kb = kk * 8 + tig;
            uint32_t af[2][4];
#pragma unroll
            for (int mf = 0; mf < 2; ++mf) {
                const int m = wm + mf * 16 + grp;
                float2 a0 = *(const float2*)(sA + m * PADA + ka);
                float2 a1 = *(const float2*)(sA + (m + 8) * PADA + ka);
                float2 a2 = *(const float2*)(sA + m * PADA + ka + 8);
                float2 a3 = *(const float2*)(sA + (m + 8) * PADA + ka + 8);
                af[mf][0] = pack_f16x2(a0.x, a0.y);
                af[mf][1] = pack_f16x2(a1.x, a1.y);
                af[mf][2] = pack_f16x2(a2.x, a2.y);
                af[mf][3] = pack_f16x2(a3.x, a3.y);
            }
#pragma unroll
            for (int nf = 0; nf < 8; ++nf) {
                const int n = wn + nf * 8 + grp;
                uint32_t bf[2];
                bf[0] = sB[n * PADB + kb];
                bf[1] = sB[n * PADB + kb + 4];
#pragma unroll
                for (int mf = 0; mf < 2; ++mf)
                    mma_m16n8k16_f16(acc[mf][nf], af[mf], bf);
            }
        }
    }

#pragma unroll
    for (int mf = 0; mf < 2; ++mf) {
        const int mlo = m0 + wm + mf * 16 + grp;
#pragma unroll
        for (int nf = 0; nf < 8; ++nf) {
            const int col = wn + nf * 8 + 2 * tig;
            const float bx = __ldg(&bias[col]);
            const float by = __ldg(&bias[col + 1]);
            if (mlo < M) {
                float2 v = make_float2(acc[mf][nf][0] + bx, acc[mf][nf][1] + by);
                *(float2*)(C + (size_t)mlo * DM + col) = v;
            }
            if (mlo + 8 < M) {
                float2 v = make_float2(acc[mf][nf][2] + bx, acc[mf][nf][3] + by);
                *(float2*)(C + (size_t)(mlo + 8) * DM + col) = v;
            }
        }
    }
}

// ===========================================================================
// Split-fp16 TC GEMM for offsets+attn: C[4800,288] = hs @ Woa^T + b
// 3-term compensated fp16: C = Ah*Bh + Ah*Bl + Al*Bh (error ~2e-7).
// ===========================================================================
#define DAW     (64 * PADA)
#define DBW     (320 * PADB)
#define DSTAGEW (DAW + 2 * DBW)
#define DNSTAGE 3

__global__ __launch_bounds__(256) void gemm_dual_tc(
    const float* __restrict__ A,
    const __half* __restrict__ Whi, const __half* __restrict__ Wlo,
    const float* __restrict__ bias, float* __restrict__ C, int M)
{
    extern __shared__ uint32_t sm[];

    const int tid  = threadIdx.x;
    const int wid  = tid >> 5;
    const int lane = tid & 31;
    const int grp  = lane >> 2;
    const int tig  = lane & 3;

    const int wm = (wid & 1) * 32;
    const int wn = (wid >> 1) * 80;
    const int m0 = blockIdx.x * 64;

    const uint32_t smem_u32 = (uint32_t)__cvta_generic_to_shared(sm);

    float acc[2][10][4];
#pragma unroll
    for (int i = 0; i < 2; i++)
#pragma unroll
        for (int j = 0; j < 10; j++)
#pragma unroll
            for (int l = 0; l < 4; l++) acc[i][j][l] = 0.f;

    auto issue = [&](int c, int s) {
        const uint32_t abase  = smem_u32 + (uint32_t)(s * DSTAGEW) * 4u;
        const uint32_t bhbase = abase + (uint32_t)DAW * 4u;
        const uint32_t blbase = bhbase + (uint32_t)DBW * 4u;
        const int k0 = c * CBK;
#pragma unroll
        for (int it = 0; it < 2; ++it) {
            int idx = tid + it * 256;
            int row = idx >> 3, col = idx & 7;
            bool v = (m0 + row) < M;
            const float* src = A + (size_t)(m0 + row) * GK + k0 + col * 4;
            cp_async16(abase + (uint32_t)(row * PADA + col * 4) * 4u, src, v);
        }
#pragma unroll
        for (int it = 0; it < 5; ++it) {
            int idx = tid + it * 256;
            int row = idx >> 2, col = idx & 3;
            const __half* srch = Whi + (size_t)row * GK + k0 + col * 8;
            cp_async16(bhbase + (uint32_t)(row * PADB + col * 4) * 4u, srch, true);
        }
#pragma unroll
        for (int it = 0; it < 5; ++it) {
            int idx = tid + it * 256;
            int row = idx >> 2, col = idx & 3;
            const __half* srcl = Wlo + (size_t)row * GK + k0 + col * 8;
            cp_async16(blbase + (uint32_t)(row * PADB + col * 4) * 4u, srcl, true);
        }
        CP_COMMIT();
    };

    issue(0, 0);
    issue(1, 1);

    for (int c = 0; c < CNCH; ++c) {
        CP_WAIT(1);
        __syncthreads();

        if (c + 2 < CNCH) issue(c + 2, (c + 2) % DNSTAGE);
        else CP_COMMIT();

        const uint32_t* sAw = sm + (c % DNSTAGE) * DSTAGEW;
        const float*    sA  = (const float*)sAw;
        const uint32_t* sBh = sAw + DAW;
        const uint32_t* sBl = sBh + DBW;

#pragma unroll
        for (int kk = 0; kk < 2; ++kk) {
            const int ka = kk * 16 + 2 * tig;
            const int kb = kk * 8 + tig;
            uint32_t ah[2][4], al[2][4];
#pragma unroll
            for (int mf = 0; mf < 2; ++mf) {
                const int m = wm + mf * 16 + grp;
                float2 a0 = *(const float2*)(sA + m * PADA + ka);
                float2 a1 = *(const float2*)(sA + (m + 8) * PADA + ka);
                float2 a2 = *(const float2*)(sA + m * PADA + ka + 8);
                float2 a3 = *(const float2*)(sA + (m + 8) * PADA + ka + 8);
#pragma unroll
                for (int q = 0; q < 4; ++q) {
                    float2 av = (q == 0) ? a0 : (q == 1) ? a1 : (q == 2) ? a2 : a3;
                    uint32_t hi = pack_f16x2(av.x, av.y);
                    float2 hf = __half22float2(*(__half2*)&hi);
                    ah[mf][q] = hi;
                    al[mf][q] = pack_f16x2(av.x - hf.x, av.y - hf.y);
                }
            }
#pragma unroll
            for (int nf = 0; nf < 10; ++nf) {
                const int n = wn + nf * 8 + grp;
                uint32_t bh[2], bl[2];
                bh[0] = sBh[n * PADB + kb];
                bh[1] = sBh[n * PADB + kb + 4];
                bl[0] = sBl[n * PADB + kb];
                bl[1] = sBl[n * PADB + kb + 4];
#pragma unroll
                for (int mf = 0; mf < 2; ++mf) {
                    mma_m16n8k16_f16(acc[mf][nf], ah[mf], bh);
                    mma_m16n8k16_f16(acc[mf][nf], ah[mf], bl);
                    mma_m16n8k16_f16(acc[mf][nf], al[mf], bh);
                }
            }
        }
    }

#pragma unroll
    for (int mf = 0; mf < 2; ++mf) {
        const int mlo = m0 + wm + mf * 16 + grp;
#pragma unroll
        for (int nf = 0; nf < 10; ++nf) {
            const int col = wn + nf * 8 + 2 * tig;
            if (col >= 288) continue;
            const float bx = __ldg(&bias[col]);
            const float by = __ldg(&bias[col + 1]);
            if (mlo < M) {
                float2 v = make_float2(acc[mf][nf][0] + bx, acc[mf][nf][1] + by);
                *(float2*)(C + (size_t)mlo * 288 + col) = v;
            }
            if (mlo + 8 < M) {
                float2 v = make_float2(acc[mf][nf][2] + bx, acc[mf][nf][3] + by);
                *(float2*)(C + (size_t)(mlo + 8) * 288 + col) = v;
            }
        }
    }
}

// ---------------------------------------------------------------------------
// Sampling kernel: block per (b,q). value is fp16 (L2-resident at 68.8 MB).
// ---------------------------------------------------------------------------
__global__ __launch_bounds__(256) void msda_sample2(
    const __half* __restrict__ value,
    const float* __restrict__ oa,
    const float* __restrict__ refp,
    float* __restrict__ out)
{
    __shared__ float  s_logit[96];
    __shared__ float2 s_mxinv[8];
    __shared__ int4   s_ofs[96];
    __shared__ float4 s_wts[96];

    const int bq = blockIdx.x;
    const int b  = bq / Q_;
    const int t  = threadIdx.x;

    if (t < 96) s_logit[t] = oa[(size_t)bq * 288 + 192 + t];
    __syncthreads();

    if (t < 8) {
        float mx = -1e30f;
#pragma unroll
        for (int p = 0; p < LP_; p++) mx = fmaxf(mx, s_logit[t * LP_ + p]);
        float s = 0.f;
#pragma unroll
        for (int p = 0; p < LP_; p++) s += __expf(s_logit[t * LP_ + p] - mx);
        s_mxinv[t] = make_float2(mx, 1.f / s);
    }
    __syncthreads();

    if (t < 96) {
        const int h = t / LP_;
        const int p = t - h * LP_;
        const float2 mi = s_mxinv[h];
        const float aw = __expf(s_logit[t] - mi.x) * mi.y;

        const float rx = refp[bq * 4 + 0];
        const float ry = refp[bq * 4 + 1];
        const float rw = refp[bq * 4 + 2];
        const float rh = refp[bq * 4 + 3];

        const float ox = oa[(size_t)bq * 288 + h * 24 + 2 * p + 0];
        const float oy = oa[(size_t)bq * 288 + h * 24 + 2 * p + 1];

        const int lvl   = p >> 2;
        const int Wl    = (lvl == 0) ? 80 : (lvl == 1) ? 40 : 20;
        const int start = (lvl == 0) ? 0 : (lvl == 1) ? 6400 : 8000;

        const float gx = (rx + ox * 0.125f * rw) * (float)Wl - 0.5f;
        const float gy = (ry + oy * 0.125f * rh) * (float)Wl - 0.5f;

        const float x0f = floorf(gx), y0f = floorf(gy);
        const int x0 = (int)x0f, y0 = (int)y0f;
        const int x1 = x0 + 1,  y1 = y0 + 1;
        const float wx1 = gx - x0f, wx0 = 1.f - wx1;
        const float wy1 = gy - y0f, wy0 = 1.f - wy1;

        const bool xv0 = (x0 >= 0) & (x0 < Wl);
        const bool xv1 = (x1 >= 0) & (x1 < Wl);
        const bool yv0 = (y0 >= 0) & (y0 < Wl);
        const bool yv1 = (y1 >= 0) & (y1 < Wl);

        const int x0c = min(max(x0, 0), Wl - 1);
        const int x1c = min(max(x1, 0), Wl - 1);
        const int y0c = min(max(y0, 0), Wl - 1);
        const int y1c = min(max(y1, 0), Wl - 1);

        const int rb = b * S_ + start;
        const int r0 = rb + y0c * Wl;
        const int r1 = rb + y1c * Wl;
        const int hb = h * HD;

        int4 o;
        o.x = (r0 + x0c) * DM + hb;
        o.y = (r0 + x1c) * DM + hb;
        o.z = (r1 + x0c) * DM + hb;
        o.w = (r1 + x1c) * DM + hb;

        float4 w;
        w.x = aw * wx0 * wy0 * (float)(xv0 & yv0);
        w.y = aw * wx1 * wy0 * (float)(xv1 & yv0);
        w.z = aw * wx0 * wy1 * (float)(xv0 & yv1);
        w.w = aw * wx1 * wy1 * (float)(xv1 & yv1);

        s_ofs[t] = o;
        s_wts[t] = w;
    }
    __syncthreads();

    const int h    = t >> 5;
    const int lane = t & 31;
    float acc = 0.f;
#pragma unroll
    for (int p = 0; p < LP_; p++) {
        const int4   o = s_ofs[h * LP_ + p];
        const float4 w = s_wts[h * LP_ + p];
        acc += w.x * __half2float(__ldg(&value[o.x + lane]));
        acc += w.y * __half2float(__ldg(&value[o.y + lane]));
        acc += w.z * __half2float(__ldg(&value[o.z + lane]));
        acc += w.w * __half2float(__ldg(&value[o.w + lane]));
    }
    out[(size_t)bq * DM + h * HD + lane] = acc;
}

// ---------------------------------------------------------------------------
extern "C" void kernel_launch(void* const* d_in, const int* in_sizes, int n_in,
                              void* d_out, int out_size)
{
    const float* hs      = (const float*)d_in[0];
    const float* ehs     = (const float*)d_in[1];
    const float* refp    = (const float*)d_in[2];
    const float* w_value = (const float*)d_in[3];
    const float* b_value = (const float*)d_in[4];
    const float* w_off   = (const float*)d_in[5];
    const float* b_off   = (const float*)d_in[6];
    const float* w_attn  = (const float*)d_in[7];
    const float* b_attn  = (const float*)d_in[8];
    const float* w_out   = (const float*)d_in[9];
    const float* b_out   = (const float*)d_in[10];
    float* out = (float*)d_out;

    float  *poa, *pmsda, *pboa;
    __half *pvalh, *pwv, *pwo, *pwhi, *pwlo;
    cudaGetSymbolAddress((void**)&pvalh, g_value_h);
    cudaGetSymbolAddress((void**)&poa,   g_oa);
    cudaGetSymbolAddress((void**)&pmsda, g_msda);
    cudaGetSymbolAddress((void**)&pwv,   g_wv_h);
    cudaGetSymbolAddress((void**)&pwo,   g_wo_h);
    cudaGetSymbolAddress((void**)&pwhi,  g_woa_hi);
    cudaGetSymbolAddress((void**)&pwlo,  g_woa_lo);
    cudaGetSymbolAddress((void**)&pboa,  g_boa);

    const int smem_big  = VNSTAGE * VSTAGEW * 4;   // 163840 B
    const int smem_sml  = CNSTAGE * CSTAGEW * 4;   // 92160 B
    const int smem_dual = DNSTAGE * DSTAGEW * 4;   // 184320 B
    cudaFuncSetAttribute(gemm_value_big,
                         cudaFuncAttributeMaxDynamicSharedMemorySize, smem_big);
    cudaFuncSetAttribute(gemm_small,
                         cudaFuncAttributeMaxDynamicSharedMemorySize, smem_sml);
    cudaFuncSetAttribute(gemm_dual_tc,
                         cudaFuncAttributeMaxDynamicSharedMemorySize, smem_dual);

    // 0. weight prep (single launch)
    prep_weights<<<832, 256>>>(w_value, w_out, w_off, b_off, w_attn, b_attn,
                               pwv, pwo, pwhi, pwlo, pboa);

    // 1. value = ehs @ w_value^T + b_value  (fp16 output, big tile)
    gemm_value_big<<<MVAL / 128, 256, smem_big>>>(ehs, pwv, b_value, pvalh, MVAL);
    // 2. offsets+attn projection (split-fp16 TC)
    gemm_dual_tc<<<BQ / 64, 256, smem_dual>>>(hs, pwhi, pwlo, pboa, poa, BQ);
    // 3. softmax + bilinear sampling + weighted sum (fp16 value reads)
    msda_sample2<<<BQ, 256>>>(pvalh, poa, refp, pmsda);
    // 4. out = msda @ w_out^T + b_out  (fp32 output, small tile)
    gemm_small<<<BQ / 64, 256, smem_sml>>>(pmsda, pwo, b_out, out, BQ);
}

// round 12
// speedup vs baseline: 1.5114x; 1.1125x over previous
#include <cuda_runtime.h>
#include <cuda_fp16.h>
#include <cstdint>
#include <math.h>

// Problem constants
#define B_   16
#define Q_   300
#define S_   8400
#define DM   256
#define NH   8
#define HD   32
#define LP_  12
#define BQ   (B_*Q_)          // 4800
#define MVAL (B_*S_)          // 134400

// Scratch (static device globals — no allocation)
__device__ __half g_value_h[(size_t)MVAL * DM];  // [B,S,256] fp16 (68.8 MB)
__device__ float  g_oa[(size_t)BQ * 288];        // offsets(192)+attn logits(96)
__device__ float  g_msda[(size_t)BQ * DM];       // sampled output fp32
__device__ __half g_wv_h[DM * DM];               // w_value fp16
__device__ __half g_wo_h[DM * DM];               // w_out fp16
__device__ __half g_woa_hi[320 * DM];            // fused off+attn W, fp16 hi
__device__ __half g_woa_lo[320 * DM];            // fused off+attn W, fp16 lo
__device__ float  g_boa[320];                    // fused bias

// ===========================================================================
// One-shot weight prep
// ===========================================================================
__global__ __launch_bounds__(256) void prep_weights(
    const float* __restrict__ Wv, const float* __restrict__ Wo,
    const float* __restrict__ Woff,  const float* __restrict__ boff,
    const float* __restrict__ Wattn, const float* __restrict__ battn,
    __half* __restrict__ wv_h, __half* __restrict__ wo_h,
    __half* __restrict__ whi, __half* __restrict__ wlo,
    float* __restrict__ boa)
{
    const int r = blockIdx.x;
    const int k = threadIdx.x;
    if (r < 256) {
        wv_h[r * DM + k] = __float2half_rn(Wv[r * DM + k]);
    } else if (r < 512) {
        int rr = r - 256;
        wo_h[rr * DM + k] = __float2half_rn(Wo[rr * DM + k]);
    } else {
        int rr = r - 512;           // 0..319
        float v = 0.f;
        if (rr < 192)      v = Woff[rr * DM + k];
        else if (rr < 288) v = Wattn[(rr - 192) * DM + k];
        __half h = __float2half_rn(v);
        whi[rr * DM + k] = h;
        wlo[rr * DM + k] = __float2half_rn(v - __half2float(h));
        if (k == 0) boa[rr] = (rr < 192) ? boff[rr]
                                         : (rr < 288 ? battn[rr - 192] : 0.f);
    }
}

// ===========================================================================
// helpers
// ===========================================================================
__device__ __forceinline__ void mma_m16n8k16_f16(
    float c[4], const uint32_t a[4], const uint32_t b[2])
{
    asm volatile(
        "mma.sync.aligned.m16n8k16.row.col.f32.f16.f16.f32 "
        "{%0,%1,%2,%3}, {%4,%5,%6,%7}, {%8,%9}, {%0,%1,%2,%3};"
        : "+f"(c[0]), "+f"(c[1]), "+f"(c[2]), "+f"(c[3])
        : "r"(a[0]), "r"(a[1]), "r"(a[2]), "r"(a[3]),
          "r"(b[0]), "r"(b[1]));
}
__device__ __forceinline__ uint32_t pack_f16x2(float lo, float hi) {
    uint32_t r;
    asm("cvt.rn.f16x2.f32 %0, %1, %2;" : "=r"(r) : "f"(hi), "f"(lo));
    return r;
}
__device__ __forceinline__ void cp_async16(uint32_t dst, const void* src, bool valid) {
    int sz = valid ? 16 : 0;
    asm volatile("cp.async.cg.shared.global [%0], [%1], 16, %2;"
                 :: "r"(dst), "l"(src), "r"(sz));
}
#define CP_COMMIT()  asm volatile("cp.async.commit_group;" ::: "memory")
#define CP_WAIT(N)   asm volatile("cp.async.wait_group %0;" :: "n"(N) : "memory")

#define GK   256
#define CBK  32

// ---- value-path tile constants (128x256, 4 stages) ----
#define VPADA   40
#define VPADB   20
#define VAW     (128 * VPADA)    // 5120 words
#define VBW     (256 * VPADB)    // 5120 words
#define VSTAGEW (VAW + VBW)      // 10240 words = 40960 B
#define VNCH    8
#define VGRID   (MVAL / 128)     // 1050

// ---- dual-path tile constants (64x160, 3 stages) ----
#define DPADA   40
#define DPADB   20
#define D2AW    (64 * DPADA)     // 2560 words
#define D2BW    (160 * DPADB)    // 3200 words
#define D2STAGEW (D2AW + 2 * D2BW)  // 8960 words = 35840 B
#define DGRID   150              // 75 m-tiles x 2 n-tiles

// unified dynamic smem = 4 * VSTAGEW = 163840 B  (>= 3 * D2STAGEW = 107520)
#define FUSED_SMEM (4 * VSTAGEW * 4)

// ===========================================================================
// FUSED kernel: blocks [0,1050) -> value GEMM 128x256 tiles (fp16 out)
//               blocks [1050,1200) -> dual split-fp16 projection 64x160 tiles
// Dual CTAs are scheduled last and fill the value GEMM's partial tail wave.
// ===========================================================================
__global__ __launch_bounds__(256, 1) void fused_value_dual(
    const float* __restrict__ Aval, const __half* __restrict__ Wv,
    const float* __restrict__ bval, __half* __restrict__ Cval,
    const float* __restrict__ Adual,
    const __half* __restrict__ Whi, const __half* __restrict__ Wlo,
    const float* __restrict__ bdual, float* __restrict__ Cdual)
{
    extern __shared__ uint32_t sm[];

    const int tid  = threadIdx.x;
    const int wid  = tid >> 5;
    const int lane = tid & 31;
    const int grp  = lane >> 2;
    const int tig  = lane & 3;
    const uint32_t smem_u32 = (uint32_t)__cvta_generic_to_shared(sm);

    if (blockIdx.x < VGRID) {
        // ================= VALUE PATH =================
        const int wm = (wid & 3) * 32;
        const int wn = (wid >> 2) * 128;
        const int m0 = blockIdx.x * 128;

        float acc[2][16][4];
#pragma unroll
        for (int i = 0; i < 2; i++)
#pragma unroll
            for (int j = 0; j < 16; j++)
#pragma unroll
                for (int l = 0; l < 4; l++) acc[i][j][l] = 0.f;

        auto issue = [&](int c, int s) {
            const uint32_t abase = smem_u32 + (uint32_t)(s * VSTAGEW) * 4u;
            const uint32_t bbase = abase + (uint32_t)VAW * 4u;
            const int k0 = c * CBK;
#pragma unroll
            for (int it = 0; it < 4; ++it) {
                int idx = tid + it * 256;
                int row = idx >> 3, col = idx & 7;
                const float* src = Aval + (size_t)(m0 + row) * GK + k0 + col * 4;
                cp_async16(abase + (uint32_t)(row * VPADA + col * 4) * 4u, src, true);
            }
#pragma unroll
            for (int it = 0; it < 4; ++it) {
                int idx = tid + it * 256;
                int row = idx >> 2, col = idx & 3;
                const __half* src = Wv + (size_t)row * GK + k0 + col * 8;
                cp_async16(bbase + (uint32_t)(row * VPADB + col * 4) * 4u, src, true);
            }
            CP_COMMIT();
        };

        issue(0, 0); issue(1, 1); issue(2, 2);

        for (int c = 0; c < VNCH; ++c) {
            CP_WAIT(2);
            __syncthreads();

            if (c + 3 < VNCH) issue(c + 3, (c + 3) & 3);
            else CP_COMMIT();

            const uint32_t* sAw = sm + (c & 3) * VSTAGEW;
            const float*    sA  = (const float*)sAw;
            const uint32_t* sB  = sAw + VAW;

#pragma unroll
            for (int kk = 0; kk < 2; ++kk) {
                const int ka = kk * 16 + 2 * tig;
                const int kb = kk * 8 + tig;
                uint32_t af[2][4];
#pragma unroll
                for (int mf = 0; mf < 2; ++mf) {
                    const int m = wm + mf * 16 + grp;
                    float2 a0 = *(const float2*)(sA + m * VPADA + ka);
                    float2 a1 = *(const float2*)(sA + (m + 8) * VPADA + ka);
                    float2 a2 = *(const float2*)(sA + m * VPADA + ka + 8);
                    float2 a3 = *(const float2*)(sA + (m + 8) * VPADA + ka + 8);
                    af[mf][0] = pack_f16x2(a0.x, a0.y);
                    af[mf][1] = pack_f16x2(a1.x, a1.y);
                    af[mf][2] = pack_f16x2(a2.x, a2.y);
                    af[mf][3] = pack_f16x2(a3.x, a3.y);
                }
#pragma unroll
                for (int nf = 0; nf < 16; ++nf) {
                    const int n = wn + nf * 8 + grp;
                    uint32_t bf[2];
                    bf[0] = sB[n * VPADB + kb];
                    bf[1] = sB[n * VPADB + kb + 4];
#pragma unroll
                    for (int mf = 0; mf < 2; ++mf)
                        mma_m16n8k16_f16(acc[mf][nf], af[mf], bf);
                }
            }
        }

#pragma unroll
        for (int mf = 0; mf < 2; ++mf) {
            const int mlo = m0 + wm + mf * 16 + grp;
#pragma unroll
            for (int nf = 0; nf < 16; ++nf) {
                const int col = wn + nf * 8 + 2 * tig;
                const float bx = __ldg(&bval[col]);
                const float by = __ldg(&bval[col + 1]);
                uint32_t p0 = pack_f16x2(acc[mf][nf][0] + bx, acc[mf][nf][1] + by);
                uint32_t p1 = pack_f16x2(acc[mf][nf][2] + bx, acc[mf][nf][3] + by);
                *(uint32_t*)(Cval + (size_t)mlo * DM + col) = p0;
                *(uint32_t*)(Cval + (size_t)(mlo + 8) * DM + col) = p1;
            }
        }
    } else {
        // ================= DUAL PATH (split-fp16, 64x160 tiles) =================
        const int bid = blockIdx.x - VGRID;     // 0..149
        const int m0  = (bid >> 1) * 64;
        const int bn0 = (bid & 1) * 160;

        const int wm = (wid & 1) * 32;
        const int wnl = (wid >> 1) * 40;

        float acc[2][5][4];
#pragma unroll
        for (int i = 0; i < 2; i++)
#pragma unroll
            for (int j = 0; j < 5; j++)
#pragma unroll
                for (int l = 0; l < 4; l++) acc[i][j][l] = 0.f;

        auto issue = [&](int c, int s) {
            const uint32_t abase  = smem_u32 + (uint32_t)(s * D2STAGEW) * 4u;
            const uint32_t bhbase = abase + (uint32_t)D2AW * 4u;
            const uint32_t blbase = bhbase + (uint32_t)D2BW * 4u;
            const int k0 = c * CBK;
#pragma unroll
            for (int it = 0; it < 2; ++it) {
                int idx = tid + it * 256;
                int row = idx >> 3, col = idx & 7;
                const float* src = Adual + (size_t)(m0 + row) * GK + k0 + col * 4;
                cp_async16(abase + (uint32_t)(row * DPADA + col * 4) * 4u, src, true);
            }
            // Bhi/Blo: 160 rows x 4 chunks = 640 each
#pragma unroll
            for (int it = 0; it < 3; ++it) {
                int idx = tid + it * 256;
                if (idx < 640) {
                    int row = idx >> 2, col = idx & 3;
                    const __half* src = Whi + (size_t)(bn0 + row) * GK + k0 + col * 8;
                    cp_async16(bhbase + (uint32_t)(row * DPADB + col * 4) * 4u, src, true);
                }
            }
#pragma unroll
            for (int it = 0; it < 3; ++it) {
                int idx = tid + it * 256;
                if (idx < 640) {
                    int row = idx >> 2, col = idx & 3;
                    const __half* src = Wlo + (size_t)(bn0 + row) * GK + k0 + col * 8;
                    cp_async16(blbase + (uint32_t)(row * DPADB + col * 4) * 4u, src, true);
                }
            }
            CP_COMMIT();
        };

        issue(0, 0); issue(1, 1);

        for (int c = 0; c < 8; ++c) {
            CP_WAIT(1);
            __syncthreads();

            if (c + 2 < 8) issue(c + 2, (c + 2) % 3);
            else CP_COMMIT();

            const uint32_t* sAw = sm + (c % 3) * D2STAGEW;
            const float*    sA  = (const float*)sAw;
            const uint32_t* sBh = sAw + D2AW;
            const uint32_t* sBl = sBh + D2BW;

#pragma unroll
            for (int kk = 0; kk < 2; ++kk) {
                const int ka = kk * 16 + 2 * tig;
                const int kb = kk * 8 + tig;
                uint32_t ah[2][4], al[2][4];
#pragma unroll
                for (int mf = 0; mf < 2; ++mf) {
                    const int m = wm + mf * 16 + grp;
                    float2 a0 = *(const float2*)(sA + m * DPADA + ka);
                    float2 a1 = *(const float2*)(sA + (m + 8) * DPADA + ka);
                    float2 a2 = *(const float2*)(sA + m * DPADA + ka + 8);
                    float2 a3 = *(const float2*)(sA + (m + 8) * DPADA + ka + 8);
#pragma unroll
                    for (int q = 0; q < 4; ++q) {
                        float2 av = (q == 0) ? a0 : (q == 1) ? a1 : (q == 2) ? a2 : a3;
                        uint32_t hi = pack_f16x2(av.x, av.y);
                        float2 hf = __half22float2(*(__half2*)&hi);
                        ah[mf][q] = hi;
                        al[mf][q] = pack_f16x2(av.x - hf.x, av.y - hf.y);
                    }
                }
#pragma unroll
                for (int nf = 0; nf < 5; ++nf) {
                    const int n = wnl + nf * 8 + grp;
                    uint32_t bh[2], bl[2];
                    bh[0] = sBh[n * DPADB + kb];
                    bh[1] = sBh[n * DPADB + kb + 4];
                    bl[0] = sBl[n * DPADB + kb];
                    bl[1] = sBl[n * DPADB + kb + 4];
#pragma unroll
                    for (int mf = 0; mf < 2; ++mf) {
                        mma_m16n8k16_f16(acc[mf][nf], ah[mf], bh);
                        mma_m16n8k16_f16(acc[mf][nf], ah[mf], bl);
                        mma_m16n8k16_f16(acc[mf][nf], al[mf], bh);
                    }
                }
            }
        }

#pragma unroll
        for (int mf = 0; mf < 2; ++mf) {
            const int mlo = m0 + wm + mf * 16 + grp;
#pragma unroll
            for (int nf = 0; nf < 5; ++nf) {
                const int col = bn0 + wnl + nf * 8 + 2 * tig;
                if (col >= 288) continue;
                const float bx = __ldg(&bdual[col]);
                const float by = __ldg(&bdual[col + 1]);
                float2 v0 = make_float2(acc[mf][nf][0] + bx, acc[mf][nf][1] + by);
                float2 v1 = make_float2(acc[mf][nf][2] + bx, acc[mf][nf][3] + by);
                *(float2*)(Cdual + (size_t)mlo * 288 + col) = v0;
                *(float2*)(Cdual + (size_t)(mlo + 8) * 288 + col) = v1;
            }
        }
    }
}

// ===========================================================================
// 64-tile mixed GEMM (out-projection): C fp32 = f16(A_f32) @ W_f16^T + bias
// ===========================================================================
#define CAW     (64 * VPADA)
#define CBW     (256 * VPADB)
#define CSTAGEW (CAW + CBW)
#define CNSTAGE 3

__global__ __launch_bounds__(256, 2) void gemm_small(
    const float* __restrict__ A, const __half* __restrict__ W,
    const float* __restrict__ bias, float* __restrict__ C, int M)
{
    extern __shared__ uint32_t sm[];

    const int tid  = threadIdx.x;
    const int wid  = tid >> 5;
    const int lane = tid & 31;
    const int grp  = lane >> 2;
    const int tig  = lane & 3;

    const int wm = (wid & 1) * 32;
    const int wn = (wid >> 1) * 64;
    const int m0 = blockIdx.x * 64;

    const uint32_t smem_u32 = (uint32_t)__cvta_generic_to_shared(sm);

    float acc[2][8][4];
#pragma unroll
    for (int i = 0; i < 2; i++)
#pragma unroll
        for (int j = 0; j < 8; j++)
#pragma unroll
            for (int l = 0; l < 4; l++) acc[i][j][l] = 0.f;

    auto issue = [&](int c, int s) {
        const uint32_t abase = smem_u32 + (uint32_t)(s * CSTAGEW) * 4u;
        const uint32_t bbase = abase + (uint32_t)CAW * 4u;
        const int k0 = c * CBK;
#pragma unroll
        for (int it = 0; it < 2; ++it) {
            int idx = tid + it * 256;
            int row = idx >> 3, col = idx & 7;
            bool v = (m0 + row) < M;
            const float* src = A + (size_t)(m0 + row) * GK + k0 + col * 4;
            cp_async16(abase + (uint32_t)(row * VPADA + col * 4) * 4u, src, v);
        }
#pragma unroll
        for (int it = 0; it < 4; ++it) {
            int idx = tid + it * 256;
            int row = idx >> 2, col = idx & 3;
            const __half* src = W + (size_t)row * GK + k0 + col * 8;
            cp_async16(bbase + (uint32_t)(row * VPADB + col * 4) * 4u, src, true);
        }
        CP_COMMIT();
    };

    issue(0, 0);
    issue(1, 1);

    for (int c = 0; c < 8; ++c) {
        CP_WAIT(1);
        __syncthreads();

        if (c + 2 < 8) issue(c + 2, (c + 2) % CNSTAGE);
        else CP_COMMIT();

        const uint32_t* sAw = sm + (c % CNSTAGE) * CSTAGEW;
        const float*    sA  = (const float*)sAw;
        const uint32_t* sB  = sAw + CAW;

#pragma unroll
        for (int kk = 0; kk < 2; ++kk) {
            const int ka = kk * 16 + 2 * tig;
            const int kb = kk * 8 + tig;
            uint32_t af[2][4];
#pragma unroll
            for (int mf = 0; mf < 2; ++mf) {
                const int m = wm + mf * 16 + grp;
                float2 a0 = *(const float2*)(sA + m * VPADA + ka);
                float2 a1 = *(const float2*)(sA + (m + 8) * VPADA + ka);
                float2 a2 = *(const float2*)(sA + m * VPADA + ka + 8);
                float2 a3 = *(const float2*)(sA + (m + 8) * VPADA + ka + 8);
                af[mf][0] = pack_f16x2(a0.x, a0.y);
                af[mf][1] = pack_f16x2(a1.x, a1.y);
                af[mf][2] = pack_f16x2(a2.x, a2.y);
                af[mf][3] = pack_f16x2(a3.x, a3.y);
            }
#pragma unroll
            for (int nf = 0; nf < 8; ++nf) {
                const int n = wn + nf * 8 + grp;
                uint32_t bf[2];
                bf[0] = sB[n * VPADB + kb];
                bf[1] = sB[n * VPADB + kb + 4];
#pragma unroll
                for (int mf = 0; mf < 2; ++mf)
                    mma_m16n8k16_f16(acc[mf][nf], af[mf], bf);
            }
        }
    }

#pragma unroll
    for (int mf = 0; mf < 2; ++mf) {
        const int mlo = m0 + wm + mf * 16 + grp;
#pragma unroll
        for (int nf = 0; nf < 8; ++nf) {
            const int col = wn + nf * 8 + 2 * tig;
            const float bx = __ldg(&bias[col]);
            const float by = __ldg(&bias[col + 1]);
            if (mlo < M) {
                float2 v = make_float2(acc[mf][nf][0] + bx, acc[mf][nf][1] + by);
                *(float2*)(C + (size_t)mlo * DM + col) = v;
            }
            if (mlo + 8 < M) {
                float2 v = make_float2(acc[mf][nf][2] + bx, acc[mf][nf][3] + by);
                *(float2*)(C + (size_t)(mlo + 8) * DM + col) = v;
            }
        }
    }
}

// ---------------------------------------------------------------------------
// Sampling kernel v3: block per (b,q). Warp = head; lane = (point-parity,
// channel-pair). Each lane loads __half2 (2 channels), warp does 2 points
// per iteration -> 24 LDG/lane instead of 48. shfl_xor(16) reduction.
// ---------------------------------------------------------------------------
__global__ __launch_bounds__(256) void msda_sample3(
    const __half* __restrict__ value,
    const float* __restrict__ oa,
    const float* __restrict__ refp,
    float* __restrict__ out)
{
    __shared__ float  s_logit[96];
    __shared__ float2 s_mxinv[8];
    __shared__ int4   s_ofs[96];
    __shared__ float4 s_wts[96];

    const int bq = blockIdx.x;
    const int b  = bq / Q_;
    const int t  = threadIdx.x;

    if (t < 96) s_logit[t] = oa[(size_t)bq * 288 + 192 + t];
    __syncthreads();

    if (t < 8) {
        float mx = -1e30f;
#pragma unroll
        for (int p = 0; p < LP_; p++) mx = fmaxf(mx, s_logit[t * LP_ + p]);
        float s = 0.f;
#pragma unroll
        for (int p = 0; p < LP_; p++) s += __expf(s_logit[t * LP_ + p] - mx);
        s_mxinv[t] = make_float2(mx, 1.f / s);
    }
    __syncthreads();

    if (t < 96) {
        const int h = t / LP_;
        const int p = t - h * LP_;
        const float2 mi = s_mxinv[h];
        const float aw = __expf(s_logit[t] - mi.x) * mi.y;

        const float rx = refp[bq * 4 + 0];
        const float ry = refp[bq * 4 + 1];
        const float rw = refp[bq * 4 + 2];
        const float rh = refp[bq * 4 + 3];

        const float ox = oa[(size_t)bq * 288 + h * 24 + 2 * p + 0];
        const float oy = oa[(size_t)bq * 288 + h * 24 + 2 * p + 1];

        const int lvl   = p >> 2;
        const int Wl    = (lvl == 0) ? 80 : (lvl == 1) ? 40 : 20;
        const int start = (lvl == 0) ? 0 : (lvl == 1) ? 6400 : 8000;

        const float gx = (rx + ox * 0.125f * rw) * (float)Wl - 0.5f;
        const float gy = (ry + oy * 0.125f * rh) * (float)Wl - 0.5f;

        const float x0f = floorf(gx), y0f = floorf(gy);
        const int x0 = (int)x0f, y0 = (int)y0f;
        const int x1 = x0 + 1,  y1 = y0 + 1;
        const float wx1 = gx - x0f, wx0 = 1.f - wx1;
        const float wy1 = gy - y0f, wy0 = 1.f - wy1;

        const bool xv0 = (x0 >= 0) & (x0 < Wl);
        const bool xv1 = (x1 >= 0) & (x1 < Wl);
        const bool yv0 = (y0 >= 0) & (y0 < Wl);
        const bool yv1 = (y1 >= 0) & (y1 < Wl);

        const int x0c = min(max(x0, 0), Wl - 1);
        const int x1c = min(max(x1, 0), Wl - 1);
        const int y0c = min(max(y0, 0), Wl - 1);
        const int y1c = min(max(y1, 0), Wl - 1);

        const int rb = b * S_ + start;
        const int r0 = rb + y0c * Wl;
        const int r1 = rb + y1c * Wl;
        const int hb = h * HD;

        int4 o;
        o.x = (r0 + x0c) * DM + hb;
        o.y = (r0 + x1c) * DM + hb;
        o.z = (r1 + x0c) * DM + hb;
        o.w = (r1 + x1c) * DM + hb;

        float4 w;
        w.x = aw * wx0 * wy0 * (float)(xv0 & yv0);
        w.y = aw * wx1 * wy0 * (float)(xv1 & yv0);
        w.z = aw * wx0 * wy1 * (float)(xv0 & yv1);
        w.w = aw * wx1 * wy1 * (float)(xv1 & yv1);

        s_ofs[t] = o;
        s_wts[t] = w;
    }
    __syncthreads();

    const int h    = t >> 5;
    const int lane = t & 31;
    const int pp   = lane >> 4;     // point parity
    const int cp   = lane & 15;     // channel pair

    float2 acc = make_float2(0.f, 0.f);
#pragma unroll
    for (int pi = 0; pi < 6; ++pi) {
        const int idx = h * LP_ + pi * 2 + pp;
        const int4   o = s_ofs[idx];
        const float4 w = s_wts[idx];
        float2 f0 = __half22float2(__ldg((const __half2*)(value + o.x) + cp));
        float2 f1 = __half22float2(__ldg((const __half2*)(value + o.y) + cp));
        float2 f2 = __half22float2(__ldg((const __half2*)(value + o.z) + cp));
        float2 f3 = __half22float2(__ldg((const __half2*)(value + o.w) + cp));
        acc.x += w.x * f0.x + w.y * f1.x + w.z * f2.x + w.w * f3.x;
        acc.y += w.x * f0.y + w.y * f1.y + w.z * f2.y + w.w * f3.y;
    }
    acc.x += __shfl_xor_sync(0xffffffffu, acc.x, 16);
    acc.y += __shfl_xor_sync(0xffffffffu, acc.y, 16);
    if (pp == 0)
        *(float2*)(out + (size_t)bq * DM + h * HD + 2 * cp) = acc;
}

// ---------------------------------------------------------------------------
extern "C" void kernel_launch(void* const* d_in, const int* in_sizes, int n_in,
                              void* d_out, int out_size)
{
    const float* hs      = (const float*)d_in[0];
    const float* ehs     = (const float*)d_in[1];
    const float* refp    = (const float*)d_in[2];
    const float* w_value = (const float*)d_in[3];
    const float* b_value = (const float*)d_in[4];
    const float* w_off   = (const float*)d_in[5];
    const float* b_off   = (const float*)d_in[6];
    const float* w_attn  = (const float*)d_in[7];
    const float* b_attn  = (const float*)d_in[8];
    const float* w_out   = (const float*)d_in[9];
    const float* b_out   = (const float*)d_in[10];
    float* out = (float*)d_out;

    float  *poa, *pmsda, *pboa;
    __half *pvalh, *pwv, *pwo, *pwhi, *pwlo;
    cudaGetSymbolAddress((void**)&pvalh, g_value_h);
    cudaGetSymbolAddress((void**)&poa,   g_oa);
    cudaGetSymbolAddress((void**)&pmsda, g_msda);
    cudaGetSymbolAddress((void**)&pwv,   g_wv_h);
    cudaGetSymbolAddress((void**)&pwo,   g_wo_h);
    cudaGetSymbolAddress((void**)&pwhi,  g_woa_hi);
    cudaGetSymbolAddress((void**)&pwlo,  g_woa_lo);
    cudaGetSymbolAddress((void**)&pboa,  g_boa);

    const int smem_sml = CNSTAGE * CSTAGEW * 4;    // 92160 B
    cudaFuncSetAttribute(fused_value_dual,
                         cudaFuncAttributeMaxDynamicSharedMemorySize, FUSED_SMEM);
    cudaFuncSetAttribute(gemm_small,
                         cudaFuncAttributeMaxDynamicSharedMemorySize, smem_sml);

    // 0. weight prep (single launch)
    prep_weights<<<832, 256>>>(w_value, w_out, w_off, b_off, w_attn, b_attn,
                               pwv, pwo, pwhi, pwlo, pboa);

    // 1. fused: value GEMM (1050 CTAs) + offsets/attn projection (150 CTAs)
    fused_value_dual<<<VGRID + DGRID, 256, FUSED_SMEM>>>(
        ehs, pwv, b_value, pvalh, hs, pwhi, pwlo, pboa, poa);

    // 2. softmax + bilinear sampling + weighted sum
    msda_sample3<<<BQ, 256>>>(pvalh, poa, refp, pmsda);

    // 3. out = msda @ w_out^T + b_out
    gemm_small<<<BQ / 64, 256, smem_sml>>>(pmsda, pwo, b_out, out, BQ);
}

// round 13
// speedup vs baseline: 1.5876x; 1.0504x over previous
#include <cuda_runtime.h>
#include <cuda_fp16.h>
#include <cstdint>
#include <math.h>

// Problem constants
#define B_   16
#define Q_   300
#define S_   8400
#define DM   256
#define NH   8
#define HD   32
#define LP_  12
#define BQ   (B_*Q_)          // 4800
#define MVAL (B_*S_)          // 134400

// Scratch (static device globals — no allocation)
__device__ __half g_value_h[(size_t)MVAL * DM];  // [B,S,256] fp16 (68.8 MB)
__device__ float  g_oa[(size_t)BQ * 288];        // offsets(192)+attn logits(96)
__device__ float  g_msda[(size_t)BQ * DM];       // sampled output fp32
__device__ __half g_wv_h[DM * DM];               // w_value fp16
__device__ __half g_wo_h[DM * DM];               // w_out fp16
__device__ __half g_woa_hi[320 * DM];            // fused off+attn W, fp16 hi
__device__ __half g_woa_lo[320 * DM];            // fused off+attn W, fp16 lo
__device__ float  g_boa[320];                    // fused bias

// ===========================================================================
// One-shot weight prep
// ===========================================================================
__global__ __launch_bounds__(256) void prep_weights(
    const float* __restrict__ Wv, const float* __restrict__ Wo,
    const float* __restrict__ Woff,  const float* __restrict__ boff,
    const float* __restrict__ Wattn, const float* __restrict__ battn,
    __half* __restrict__ wv_h, __half* __restrict__ wo_h,
    __half* __restrict__ whi, __half* __restrict__ wlo,
    float* __restrict__ boa)
{
    const int r = blockIdx.x;
    const int k = threadIdx.x;
    if (r < 256) {
        wv_h[r * DM + k] = __float2half_rn(Wv[r * DM + k]);
    } else if (r < 512) {
        int rr = r - 256;
        wo_h[rr * DM + k] = __float2half_rn(Wo[rr * DM + k]);
    } else {
        int rr = r - 512;           // 0..319
        float v = 0.f;
        if (rr < 192)      v = Woff[rr * DM + k];
        else if (rr < 288) v = Wattn[(rr - 192) * DM + k];
        __half h = __float2half_rn(v);
        whi[rr * DM + k] = h;
        wlo[rr * DM + k] = __float2half_rn(v - __half2float(h));
        if (k == 0) boa[rr] = (rr < 192) ? boff[rr]
                                         : (rr < 288 ? battn[rr - 192] : 0.f);
    }
}

// ===========================================================================
// helpers
// ===========================================================================
__device__ __forceinline__ void mma_m16n8k16_f16(
    float c[4], const uint32_t a[4], const uint32_t b[2])
{
    asm volatile(
        "mma.sync.aligned.m16n8k16.row.col.f32.f16.f16.f32 "
        "{%0,%1,%2,%3}, {%4,%5,%6,%7}, {%8,%9}, {%0,%1,%2,%3};"
        : "+f"(c[0]), "+f"(c[1]), "+f"(c[2]), "+f"(c[3])
        : "r"(a[0]), "r"(a[1]), "r"(a[2]), "r"(a[3]),
          "r"(b[0]), "r"(b[1]));
}
__device__ __forceinline__ uint32_t pack_f16x2(float lo, float hi) {
    uint32_t r;
    asm("cvt.rn.f16x2.f32 %0, %1, %2;" : "=r"(r) : "f"(hi), "f"(lo));
    return r;
}
__device__ __forceinline__ void cp_async16(uint32_t dst, const void* src, bool valid) {
    int sz = valid ? 16 : 0;
    asm volatile("cp.async.cg.shared.global [%0], [%1], 16, %2;"
                 :: "r"(dst), "l"(src), "r"(sz));
}
#define CP_COMMIT()  asm volatile("cp.async.commit_group;" ::: "memory")
#define CP_WAIT(N)   asm volatile("cp.async.wait_group %0;" :: "n"(N) : "memory")

#define GK   256

// ---- value-path tile constants (128x256, BK=64, 3 stages) ----
#define VBK     64
#define VNCH    (GK / VBK)       // 4 chunks
#define VPADA   72               // fp32 words per A row (64 data + 8 pad)
#define VPADB   36               // packed f16 words per B row (32 data + 4 pad)
#define VAW     (128 * VPADA)    // 9216 words
#define VBW     (256 * VPADB)    // 9216 words
#define VSTAGEW (VAW + VBW)      // 18432 words = 73728 B
#define VGRID   (MVAL / 128)     // 1050

// ---- dual-path tile constants (64x160, BK=32, 3 stages) ----
#define DBK     32
#define DPADA   40
#define DPADB   20
#define D2AW    (64 * DPADA)     // 2560 words
#define D2BW    (160 * DPADB)    // 3200 words
#define D2STAGEW (D2AW + 2 * D2BW)  // 8960 words = 35840 B
#define DGRID   150

// unified dynamic smem = 3 * VSTAGEW = 221184 B  (>= 3 * D2STAGEW)
#define FUSED_SMEM (3 * VSTAGEW * 4)

// ===========================================================================
// FUSED kernel: blocks [0,1050) -> value GEMM 128x256 (BK=64, fp16 out)
//               blocks [1050,1200) -> dual split-fp16 projection 64x160
// ===========================================================================
__global__ __launch_bounds__(256, 1) void fused_value_dual(
    const float* __restrict__ Aval, const __half* __restrict__ Wv,
    const float* __restrict__ bval, __half* __restrict__ Cval,
    const float* __restrict__ Adual,
    const __half* __restrict__ Whi, const __half* __restrict__ Wlo,
    const float* __restrict__ bdual, float* __restrict__ Cdual)
{
    extern __shared__ uint32_t sm[];

    const int tid  = threadIdx.x;
    const int wid  = tid >> 5;
    const int lane = tid & 31;
    const int grp  = lane >> 2;
    const int tig  = lane & 3;
    const uint32_t smem_u32 = (uint32_t)__cvta_generic_to_shared(sm);

    if (blockIdx.x < VGRID) {
        // ================= VALUE PATH (BK=64, 4 chunks, 3 stages) =========
        const int wm = (wid & 3) * 32;
        const int wn = (wid >> 2) * 128;
        const int m0 = blockIdx.x * 128;

        float acc[2][16][4];
#pragma unroll
        for (int i = 0; i < 2; i++)
#pragma unroll
            for (int j = 0; j < 16; j++)
#pragma unroll
                for (int l = 0; l < 4; l++) acc[i][j][l] = 0.f;

        auto issue = [&](int c, int s) {
            const uint32_t abase = smem_u32 + (uint32_t)(s * VSTAGEW) * 4u;
            const uint32_t bbase = abase + (uint32_t)VAW * 4u;
            const int k0 = c * VBK;
            // A fp32: 128 rows x 16 16B-chunks = 2048 -> 8/thread
#pragma unroll
            for (int it = 0; it < 8; ++it) {
                int idx = tid + it * 256;
                int row = idx >> 4, col = idx & 15;
                const float* src = Aval + (size_t)(m0 + row) * GK + k0 + col * 4;
                cp_async16(abase + (uint32_t)(row * VPADA + col * 4) * 4u, src, true);
            }
            // B f16: 256 rows x 8 16B-chunks = 2048 -> 8/thread
#pragma unroll
            for (int it = 0; it < 8; ++it) {
                int idx = tid + it * 256;
                int row = idx >> 3, col = idx & 7;
                const __half* src = Wv + (size_t)row * GK + k0 + col * 8;
                cp_async16(bbase + (uint32_t)(row * VPADB + col * 4) * 4u, src, true);
            }
            CP_COMMIT();
        };

        issue(0, 0);
        issue(1, 1);

        for (int c = 0; c < VNCH; ++c) {
            CP_WAIT(1);           // chunk c resident (c+1 may be in flight)
            __syncthreads();      // visible; chunk c-1 reads done

            if (c + 2 < VNCH) issue(c + 2, (c + 2) % 3);  // stage (c-1)%3 freed
            else CP_COMMIT();

            const uint32_t* sAw = sm + (c % 3) * VSTAGEW;
            const float*    sA  = (const float*)sAw;
            const uint32_t* sB  = sAw + VAW;

#pragma unroll
            for (int kk = 0; kk < 4; ++kk) {
                const int ka = kk * 16 + 2 * tig;
                const int kb = kk * 8 + tig;
                uint32_t af[2][4];
#pragma unroll
                for (int mf = 0; mf < 2; ++mf) {
                    const int m = wm + mf * 16 + grp;
                    float2 a0 = *(const float2*)(sA + m * VPADA + ka);
                    float2 a1 = *(const float2*)(sA + (m + 8) * VPADA + ka);
                    float2 a2 = *(const float2*)(sA + m * VPADA + ka + 8);
                    float2 a3 = *(const float2*)(sA + (m + 8) * VPADA + ka + 8);
                    af[mf][0] = pack_f16x2(a0.x, a0.y);
                    af[mf][1] = pack_f16x2(a1.x, a1.y);
                    af[mf][2] = pack_f16x2(a2.x, a2.y);
                    af[mf][3] = pack_f16x2(a3.x, a3.y);
                }
#pragma unroll
                for (int nf = 0; nf < 16; ++nf) {
                    const int n = wn + nf * 8 + grp;
                    uint32_t bf[2];
                    bf[0] = sB[n * VPADB + kb];
                    bf[1] = sB[n * VPADB + kb + 4];
#pragma unroll
                    for (int mf = 0; mf < 2; ++mf)
                        mma_m16n8k16_f16(acc[mf][nf], af[mf], bf);
                }
            }
        }

#pragma unroll
        for (int mf = 0; mf < 2; ++mf) {
            const int mlo = m0 + wm + mf * 16 + grp;
#pragma unroll
            for (int nf = 0; nf < 16; ++nf) {
                const int col = wn + nf * 8 + 2 * tig;
                const float bx = __ldg(&bval[col]);
                const float by = __ldg(&bval[col + 1]);
                uint32_t p0 = pack_f16x2(acc[mf][nf][0] + bx, acc[mf][nf][1] + by);
                uint32_t p1 = pack_f16x2(acc[mf][nf][2] + bx, acc[mf][nf][3] + by);
                *(uint32_t*)(Cval + (size_t)mlo * DM + col) = p0;
                *(uint32_t*)(Cval + (size_t)(mlo + 8) * DM + col) = p1;
            }
        }
    } else {
        // ================= DUAL PATH (split-fp16, 64x160, BK=32) ==========
        const int bid = blockIdx.x - VGRID;     // 0..149
        const int m0  = (bid >> 1) * 64;
        const int bn0 = (bid & 1) * 160;

        const int wm = (wid & 1) * 32;
        const int wnl = (wid >> 1) * 40;

        float acc[2][5][4];
#pragma unroll
        for (int i = 0; i < 2; i++)
#pragma unroll
            for (int j = 0; j < 5; j++)
#pragma unroll
                for (int l = 0; l < 4; l++) acc[i][j][l] = 0.f;

        auto issue = [&](int c, int s) {
            const uint32_t abase  = smem_u32 + (uint32_t)(s * D2STAGEW) * 4u;
            const uint32_t bhbase = abase + (uint32_t)D2AW * 4u;
            const uint32_t blbase = bhbase + (uint32_t)D2BW * 4u;
            const int k0 = c * DBK;
#pragma unroll
            for (int it = 0; it < 2; ++it) {
                int idx = tid + it * 256;
                int row = idx >> 3, col = idx & 7;
                const float* src = Adual + (size_t)(m0 + row) * GK + k0 + col * 4;
                cp_async16(abase + (uint32_t)(row * DPADA + col * 4) * 4u, src, true);
            }
#pragma unroll
            for (int it = 0; it < 3; ++it) {
                int idx = tid + it * 256;
                if (idx < 640) {
                    int row = idx >> 2, col = idx & 3;
                    const __half* src = Whi + (size_t)(bn0 + row) * GK + k0 + col * 8;
                    cp_async16(bhbase + (uint32_t)(row * DPADB + col * 4) * 4u, src, true);
                }
            }
#pragma unroll
            for (int it = 0; it < 3; ++it) {
                int idx = tid + it * 256;
                if (idx < 640) {
                    int row = idx >> 2, col = idx & 3;
                    const __half* src = Wlo + (size_t)(bn0 + row) * GK + k0 + col * 8;
                    cp_async16(blbase + (uint32_t)(row * DPADB + col * 4) * 4u, src, true);
                }
            }
            CP_COMMIT();
        };

        issue(0, 0); issue(1, 1);

        for (int c = 0; c < 8; ++c) {
            CP_WAIT(1);
            __syncthreads();

            if (c + 2 < 8) issue(c + 2, (c + 2) % 3);
            else CP_COMMIT();

            const uint32_t* sAw = sm + (c % 3) * D2STAGEW;
            const float*    sA  = (const float*)sAw;
            const uint32_t* sBh = sAw + D2AW;
            const uint32_t* sBl = sBh + D2BW;

#pragma unroll
            for (int kk = 0; kk < 2; ++kk) {
                const int ka = kk * 16 + 2 * tig;
                const int kb = kk * 8 + tig;
                uint32_t ah[2][4], al[2][4];
#pragma unroll
                for (int mf = 0; mf < 2; ++mf) {
                    const int m = wm + mf * 16 + grp;
                    float2 a0 = *(const float2*)(sA + m * DPADA + ka);
                    float2 a1 = *(const float2*)(sA + (m + 8) * DPADA + ka);
                    float2 a2 = *(const float2*)(sA + m * DPADA + ka + 8);
                    float2 a3 = *(const float2*)(sA + (m + 8) * DPADA + ka + 8);
#pragma unroll
                    for (int q = 0; q < 4; ++q) {
                        float2 av = (q == 0) ? a0 : (q == 1) ? a1 : (q == 2) ? a2 : a3;
                        uint32_t hi = pack_f16x2(av.x, av.y);
                        float2 hf = __half22float2(*(__half2*)&hi);
                        ah[mf][q] = hi;
                        al[mf][q] = pack_f16x2(av.x - hf.x, av.y - hf.y);
                    }
                }
#pragma unroll
                for (int nf = 0; nf < 5; ++nf) {
                    const int n = wnl + nf * 8 + grp;
                    uint32_t bh[2], bl[2];
                    bh[0] = sBh[n * DPADB + kb];
                    bh[1] = sBh[n * DPADB + kb + 4];
                    bl[0] = sBl[n * DPADB + kb];
                    bl[1] = sBl[n * DPADB + kb + 4];
#pragma unroll
                    for (int mf = 0; mf < 2; ++mf) {
                        mma_m16n8k16_f16(acc[mf][nf], ah[mf], bh);
                        mma_m16n8k16_f16(acc[mf][nf], ah[mf], bl);
                        mma_m16n8k16_f16(acc[mf][nf], al[mf], bh);
                    }
                }
            }
        }

#pragma unroll
        for (int mf = 0; mf < 2; ++mf) {
            const int mlo = m0 + wm + mf * 16 + grp;
#pragma unroll
            for (int nf = 0; nf < 5; ++nf) {
                const int col = bn0 + wnl + nf * 8 + 2 * tig;
                if (col >= 288) continue;
                const float bx = __ldg(&bdual[col]);
                const float by = __ldg(&bdual[col + 1]);
                float2 v0 = make_float2(acc[mf][nf][0] + bx, acc[mf][nf][1] + by);
                float2 v1 = make_float2(acc[mf][nf][2] + bx, acc[mf][nf][3] + by);
                *(float2*)(Cdual + (size_t)mlo * 288 + col) = v0;
                *(float2*)(Cdual + (size_t)(mlo + 8) * 288 + col) = v1;
            }
        }
    }
}

// ===========================================================================
// Out-projection GEMM, N-split: grid 150 = 75 m-tiles x 2 n-halves.
// CTA tile 64x128, 8 warps (2m x 4n), warp tile 32x32, 2 CTAs/SM, 3 stages.
// ===========================================================================
#define OPADA   40
#define OPADB   20
#define OAW     (64 * OPADA)     // 2560 words
#define OBW     (128 * OPADB)    // 2560 words
#define OSTAGEW (OAW + OBW)      // 5120 words = 20480 B
#define ONSTAGE 3

__global__ __launch_bounds__(256, 2) void gemm_out(
    const float* __restrict__ A, const __half* __restrict__ W,
    const float* __restrict__ bias, float* __restrict__ C, int M)
{
    extern __shared__ uint32_t sm[];

    const int tid  = threadIdx.x;
    const int wid  = tid >> 5;
    const int lane = tid & 31;
    const int grp  = lane >> 2;
    const int tig  = lane & 3;

    const int m0  = (blockIdx.x >> 1) * 64;
    const int bn0 = (blockIdx.x & 1) * 128;
    const int wm  = (wid & 1) * 32;
    const int wn  = (wid >> 1) * 32;

    const uint32_t smem_u32 = (uint32_t)__cvta_generic_to_shared(sm);

    float acc[2][4][4];
#pragma unroll
    for (int i = 0; i < 2; i++)
#pragma unroll
        for (int j = 0; j < 4; j++)
#pragma unroll
            for (int l = 0; l < 4; l++) acc[i][j][l] = 0.f;

    auto issue = [&](int c, int s) {
        const uint32_t abase = smem_u32 + (uint32_t)(s * OSTAGEW) * 4u;
        const uint32_t bbase = abase + (uint32_t)OAW * 4u;
        const int k0 = c * 32;
        // A fp32: 64 rows x 8 = 512 -> 2/thread
#pragma unroll
        for (int it = 0; it < 2; ++it) {
            int idx = tid + it * 256;
            int row = idx >> 3, col = idx & 7;
            bool v = (m0 + row) < M;
            const float* src = A + (size_t)(m0 + row) * GK + k0 + col * 4;
            cp_async16(abase + (uint32_t)(row * OPADA + col * 4) * 4u, src, v);
        }
        // B f16: 128 rows x 4 = 512 -> 2/thread
#pragma unroll
        for (int it = 0; it < 2; ++it) {
            int idx = tid + it * 256;
            int row = idx >> 2, col = idx & 3;
            const __half* src = W + (size_t)(bn0 + row) * GK + k0 + col * 8;
            cp_async16(bbase + (uint32_t)(row * OPADB + col * 4) * 4u, src, true);
        }
        CP_COMMIT();
    };

    issue(0, 0);
    issue(1, 1);

    for (int c = 0; c < 8; ++c) {
        CP_WAIT(1);
        __syncthreads();

        if (c + 2 < 8) issue(c + 2, (c + 2) % ONSTAGE);
        else CP_COMMIT();

        const uint32_t* sAw = sm + (c % ONSTAGE) * OSTAGEW;
        const float*    sA  = (const float*)sAw;
        const uint32_t* sB  = sAw + OAW;

#pragma unroll
        for (int kk = 0; kk < 2; ++kk) {
            const int ka = kk * 16 + 2 * tig;
            const int kb = kk * 8 + tig;
            uint32_t af[2][4];
#pragma unroll
            for (int mf = 0; mf < 2; ++mf) {
                const int m = wm + mf * 16 + grp;
                float2 a0 = *(const float2*)(sA + m * OPADA + ka);
                float2 a1 = *(const float2*)(sA + (m + 8) * OPADA + ka);
                float2 a2 = *(const float2*)(sA + m * OPADA + ka + 8);
                float2 a3 = *(const float2*)(sA + (m + 8) * OPADA + ka + 8);
                af[mf][0] = pack_f16x2(a0.x, a0.y);
                af[mf][1] = pack_f16x2(a1.x, a1.y);
                af[mf][2] = pack_f16x2(a2.x, a2.y);
                af[mf][3] = pack_f16x2(a3.x, a3.y);
            }
#pragma unroll
            for (int nf = 0; nf < 4; ++nf) {
                const int n = wn + nf * 8 + grp;
                uint32_t bf[2];
                bf[0] = sB[n * OPADB + kb];
                bf[1] = sB[n * OPADB + kb + 4];
#pragma unroll
                for (int mf = 0; mf < 2; ++mf)
                    mma_m16n8k16_f16(acc[mf][nf], af[mf], bf);
            }
        }
    }

#pragma unroll
    for (int mf = 0; mf < 2; ++mf) {
        const int mlo = m0 + wm + mf * 16 + grp;
#pragma unroll
        for (int nf = 0; nf < 4; ++nf) {
            const int col = bn0 + wn + nf * 8 + 2 * tig;
            const float bx = __ldg(&bias[col]);
            const float by = __ldg(&bias[col + 1]);
            if (mlo < M) {
                float2 v = make_float2(acc[mf][nf][0] + bx, acc[mf][nf][1] + by);
                *(float2*)(C + (size_t)mlo * DM + col) = v;
            }
            if (mlo + 8 < M) {
                float2 v = make_float2(acc[mf][nf][2] + bx, acc[mf][nf][3] + by);
                *(float2*)(C + (size_t)(mlo + 8) * DM + col) = v;
            }
        }
    }
}

// ---------------------------------------------------------------------------
// Sampling kernel v3 (unchanged from R12).
// ---------------------------------------------------------------------------
__global__ __launch_bounds__(256) void msda_sample3(
    const __half* __restrict__ value,
    const float* __restrict__ oa,
    const float* __restrict__ refp,
    float* __restrict__ out)
{
    __shared__ float  s_logit[96];
    __shared__ float2 s_mxinv[8];
    __shared__ int4   s_ofs[96];
    __shared__ float4 s_wts[96];

    const int bq = blockIdx.x;
    const int b  = bq / Q_;
    const int t  = threadIdx.x;

    if (t < 96) s_logit[t] = oa[(size_t)bq * 288 + 192 + t];
    __syncthreads();

    if (t < 8) {
        float mx = -1e30f;
#pragma unroll
        for (int p = 0; p < LP_; p++) mx = fmaxf(mx, s_logit[t * LP_ + p]);
        float s = 0.f;
#pragma unroll
        for (int p = 0; p < LP_; p++) s += __expf(s_logit[t * LP_ + p] - mx);
        s_mxinv[t] = make_float2(mx, 1.f / s);
    }
    __syncthreads();

    if (t < 96) {
        const int h = t / LP_;
        const int p = t - h * LP_;
        const float2 mi = s_mxinv[h];
        const float aw = __expf(s_logit[t] - mi.x) * mi.y;

        const float rx = refp[bq * 4 + 0];
        const float ry = refp[bq * 4 + 1];
        const float rw = refp[bq * 4 + 2];
        const float rh = refp[bq * 4 + 3];

        const float ox = oa[(size_t)bq * 288 + h * 24 + 2 * p + 0];
        const float oy = oa[(size_t)bq * 288 + h * 24 + 2 * p + 1];

        const int lvl   = p >> 2;
        const int Wl    = (lvl == 0) ? 80 : (lvl == 1) ? 40 : 20;
        const int start = (lvl == 0) ? 0 : (lvl == 1) ? 6400 : 8000;

        const float gx = (rx + ox * 0.125f * rw) * (float)Wl - 0.5f;
        const float gy = (ry + oy * 0.125f * rh) * (float)Wl - 0.5f;

        const float x0f = floorf(gx), y0f = floorf(gy);
        const int x0 = (int)x0f, y0 = (int)y0f;
        const int x1 = x0 + 1,  y1 = y0 + 1;
        const float wx1 = gx - x0f, wx0 = 1.f - wx1;
        const float wy1 = gy - y0f, wy0 = 1.f - wy1;

        const bool xv0 = (x0 >= 0) & (x0 < Wl);
        const bool xv1 = (x1 >= 0) & (x1 < Wl);
        const bool yv0 = (y0 >= 0) & (y0 < Wl);
        const bool yv1 = (y1 >= 0) & (y1 < Wl);

        const int x0c = min(max(x0, 0), Wl - 1);
        const int x1c = min(max(x1, 0), Wl - 1);
        const int y0c = min(max(y0, 0), Wl - 1);
        const int y1c = min(max(y1, 0), Wl - 1);

        const int rb = b * S_ + start;
        const int r0 = rb + y0c * Wl;
        const int r1 = rb + y1c * Wl;
        const int hb = h * HD;

        int4 o;
        o.x = (r0 + x0c) * DM + hb;
        o.y = (r0 + x1c) * DM + hb;
        o.z = (r1 + x0c) * DM + hb;
        o.w = (r1 + x1c) * DM + hb;

        float4 w;
        w.x = aw * wx0 * wy0 * (float)(xv0 & yv0);
        w.y = aw * wx1 * wy0 * (float)(xv1 & yv0);
        w.z = aw * wx0 * wy1 * (float)(xv0 & yv1);
        w.w = aw * wx1 * wy1 * (float)(xv1 & yv1);

        s_ofs[t] = o;
        s_wts[t] = w;
    }
    __syncthreads();

    const int h    = t >> 5;
    const int lane = t & 31;
    const int pp   = lane >> 4;
    const int cp   = lane & 15;

    float2 acc = make_float2(0.f, 0.f);
#pragma unroll
    for (int pi = 0; pi < 6; ++pi) {
        const int idx = h * LP_ + pi * 2 + pp;
        const int4   o = s_ofs[idx];
        const float4 w = s_wts[idx];
        float2 f0 = __half22float2(__ldg((const __half2*)(value + o.x) + cp));
        float2 f1 = __half22float2(__ldg((const __half2*)(value + o.y) + cp));
        float2 f2 = __half22float2(__ldg((const __half2*)(value + o.z) + cp));
        float2 f3 = __half22float2(__ldg((const __half2*)(value + o.w) + cp));
        acc.x += w.x * f0.x + w.y * f1.x + w.z * f2.x + w.w * f3.x;
        acc.y += w.x * f0.y + w.y * f1.y + w.z * f2.y + w.w * f3.y;
    }
    acc.x += __shfl_xor_sync(0xffffffffu, acc.x, 16);
    acc.y += __shfl_xor_sync(0xffffffffu, acc.y, 16);
    if (pp == 0)
        *(float2*)(out + (size_t)bq * DM + h * HD + 2 * cp) = acc;
}

// ---------------------------------------------------------------------------
extern "C" void kernel_launch(void* const* d_in, const int* in_sizes, int n_in,
                              void* d_out, int out_size)
{
    const float* hs      = (const float*)d_in[0];
    const float* ehs     = (const float*)d_in[1];
    const float* refp    = (const float*)d_in[2];
    const float* w_value = (const float*)d_in[3];
    const float* b_value = (const float*)d_in[4];
    const float* w_off   = (const float*)d_in[5];
    const float* b_off   = (const float*)d_in[6];
    const float* w_attn  = (const float*)d_in[7];
    const float* b_attn  = (const float*)d_in[8];
    const float* w_out   = (const float*)d_in[9];
    const float* b_out   = (const float*)d_in[10];
    float* out = (float*)d_out;

    float  *poa, *pmsda, *pboa;
    __half *pvalh, *pwv, *pwo, *pwhi, *pwlo;
    cudaGetSymbolAddress((void**)&pvalh, g_value_h);
    cudaGetSymbolAddress((void**)&poa,   g_oa);
    cudaGetSymbolAddress((void**)&pmsda, g_msda);
    cudaGetSymbolAddress((void**)&pwv,   g_wv_h);
    cudaGetSymbolAddress((void**)&pwo,   g_wo_h);
    cudaGetSymbolAddress((void**)&pwhi,  g_woa_hi);
    cudaGetSymbolAddress((void**)&pwlo,  g_woa_lo);
    cudaGetSymbolAddress((void**)&pboa,  g_boa);

    const int smem_out = ONSTAGE * OSTAGEW * 4;    // 61440 B
    cudaFuncSetAttribute(fused_value_dual,
                         cudaFuncAttributeMaxDynamicSharedMemorySize, FUSED_SMEM);
    cudaFuncSetAttribute(gemm_out,
                         cudaFuncAttributeMaxDynamicSharedMemorySize, smem_out);

    // 0. weight prep (single launch)
    prep_weights<<<832, 256>>>(w_value, w_out, w_off, b_off, w_attn, b_attn,
                               pwv, pwo, pwhi, pwlo, pboa);

    // 1. fused: value GEMM (1050 CTAs, BK=64) + offsets/attn (150 CTAs)
    fused_value_dual<<<VGRID + DGRID, 256, FUSED_SMEM>>>(
        ehs, pwv, b_value, pvalh, hs, pwhi, pwlo, pboa, poa);

    // 2. softmax + bilinear sampling + weighted sum
    msda_sample3<<<BQ, 256>>>(pvalh, poa, refp, pmsda);

    // 3. out = msda @ w_out^T + b_out  (N-split, 150 CTAs)
    gemm_out<<<DGRID, 256, smem_out>>>(pmsda, pwo, b_out, out, BQ);
}

// round 14
// speedup vs baseline: 1.6222x; 1.0218x over previous
#include <cuda_runtime.h>
#include <cuda_fp16.h>
#include <cstdint>
#include <math.h>

// Problem constants
#define B_   16
#define Q_   300
#define S_   8400
#define DM   256
#define NH   8
#define HD   32
#define LP_  12
#define BQ   (B_*Q_)          // 4800
#define MVAL (B_*S_)          // 134400

// Scratch (static device globals — no allocation)
__device__ __half g_value_h[(size_t)MVAL * DM];  // [B,S,256] fp16 (68.8 MB)
__device__ float  g_oa[(size_t)BQ * 288];        // offsets(192)+attn logits(96)
__device__ float  g_msda[(size_t)BQ * DM];       // sampled output fp32
__device__ __half g_wv_h[DM * DM];               // w_value fp16
__device__ __half g_wo_h[DM * DM];               // w_out fp16
__device__ __half g_woa_hi[320 * DM];            // fused off+attn W, fp16 hi
__device__ __half g_woa_lo[320 * DM];            // fused off+attn W, fp16 lo
__device__ float  g_boa[320];                    // fused bias

// ===========================================================================
// One-shot weight prep
// ===========================================================================
__global__ __launch_bounds__(256) void prep_weights(
    const float* __restrict__ Wv, const float* __restrict__ Wo,
    const float* __restrict__ Woff,  const float* __restrict__ boff,
    const float* __restrict__ Wattn, const float* __restrict__ battn,
    __half* __restrict__ wv_h, __half* __restrict__ wo_h,
    __half* __restrict__ whi, __half* __restrict__ wlo,
    float* __restrict__ boa)
{
    const int r = blockIdx.x;
    const int k = threadIdx.x;
    if (r < 256) {
        wv_h[r * DM + k] = __float2half_rn(Wv[r * DM + k]);
    } else if (r < 512) {
        int rr = r - 256;
        wo_h[rr * DM + k] = __float2half_rn(Wo[rr * DM + k]);
    } else {
        int rr = r - 512;           // 0..319
        float v = 0.f;
        if (rr < 192)      v = Woff[rr * DM + k];
        else if (rr < 288) v = Wattn[(rr - 192) * DM + k];
        __half h = __float2half_rn(v);
        whi[rr * DM + k] = h;
        wlo[rr * DM + k] = __float2half_rn(v - __half2float(h));
        if (k == 0) boa[rr] = (rr < 192) ? boff[rr]
                                         : (rr < 288 ? battn[rr - 192] : 0.f);
    }
}

// ===========================================================================
// helpers
// ===========================================================================
__device__ __forceinline__ void mma_m16n8k16_f16(
    float c[4], const uint32_t a[4], const uint32_t b[2])
{
    asm volatile(
        "mma.sync.aligned.m16n8k16.row.col.f32.f16.f16.f32 "
        "{%0,%1,%2,%3}, {%4,%5,%6,%7}, {%8,%9}, {%0,%1,%2,%3};"
        : "+f"(c[0]), "+f"(c[1]), "+f"(c[2]), "+f"(c[3])
        : "r"(a[0]), "r"(a[1]), "r"(a[2]), "r"(a[3]),
          "r"(b[0]), "r"(b[1]));
}
__device__ __forceinline__ uint32_t pack_f16x2(float lo, float hi) {
    uint32_t r;
    asm("cvt.rn.f16x2.f32 %0, %1, %2;" : "=r"(r) : "f"(hi), "f"(lo));
    return r;
}
__device__ __forceinline__ void cp_async16(uint32_t dst, const void* src, bool valid) {
    int sz = valid ? 16 : 0;
    asm volatile("cp.async.cg.shared.global [%0], [%1], 16, %2;"
                 :: "r"(dst), "l"(src), "r"(sz));
}
#define CP_COMMIT()  asm volatile("cp.async.commit_group;" ::: "memory")
#define CP_WAIT(N)   asm volatile("cp.async.wait_group %0;" :: "n"(N) : "memory")

#define GK   256

// ---- value-path tile constants (128x256, BK=64, 3 stages) ----
#define VBK     64
#define VNCH    (GK / VBK)       // 4 chunks
#define VPADA   72
#define VPADB   36
#define VAW     (128 * VPADA)    // 9216 words
#define VBW     (256 * VPADB)    // 9216 words
#define VSTAGEW (VAW + VBW)      // 18432 words = 73728 B
#define VGRID   (MVAL / 128)     // 1050

// ---- dual-path tile constants (64x160, BK=32, 3 stages) ----
#define DBK     32
#define DPADA   40
#define DPADB   20
#define D2AW    (64 * DPADA)
#define D2BW    (160 * DPADB)
#define D2STAGEW (D2AW + 2 * D2BW)
#define DGRID   150

#define FUSED_SMEM (3 * VSTAGEW * 4)   // 221184 B

// ===========================================================================
// FUSED kernel: blocks [0,1050) -> value GEMM; [1050,1200) -> dual projection
// ===========================================================================
__global__ __launch_bounds__(256, 1) void fused_value_dual(
    const float* __restrict__ Aval, const __half* __restrict__ Wv,
    const float* __restrict__ bval, __half* __restrict__ Cval,
    const float* __restrict__ Adual,
    const __half* __restrict__ Whi, const __half* __restrict__ Wlo,
    const float* __restrict__ bdual, float* __restrict__ Cdual)
{
    extern __shared__ uint32_t sm[];

    const int tid  = threadIdx.x;
    const int wid  = tid >> 5;
    const int lane = tid & 31;
    const int grp  = lane >> 2;
    const int tig  = lane & 3;
    const uint32_t smem_u32 = (uint32_t)__cvta_generic_to_shared(sm);

    if (blockIdx.x < VGRID) {
        // ================= VALUE PATH =================
        const int wm = (wid & 3) * 32;
        const int wn = (wid >> 2) * 128;
        const int m0 = blockIdx.x * 128;

        float acc[2][16][4];
#pragma unroll
        for (int i = 0; i < 2; i++)
#pragma unroll
            for (int j = 0; j < 16; j++)
#pragma unroll
                for (int l = 0; l < 4; l++) acc[i][j][l] = 0.f;

        auto issue = [&](int c, int s) {
            const uint32_t abase = smem_u32 + (uint32_t)(s * VSTAGEW) * 4u;
            const uint32_t bbase = abase + (uint32_t)VAW * 4u;
            const int k0 = c * VBK;
#pragma unroll
            for (int it = 0; it < 8; ++it) {
                int idx = tid + it * 256;
                int row = idx >> 4, col = idx & 15;
                const float* src = Aval + (size_t)(m0 + row) * GK + k0 + col * 4;
                cp_async16(abase + (uint32_t)(row * VPADA + col * 4) * 4u, src, true);
            }
#pragma unroll
            for (int it = 0; it < 8; ++it) {
                int idx = tid + it * 256;
                int row = idx >> 3, col = idx & 7;
                const __half* src = Wv + (size_t)row * GK + k0 + col * 8;
                cp_async16(bbase + (uint32_t)(row * VPADB + col * 4) * 4u, src, true);
            }
            CP_COMMIT();
        };

        issue(0, 0);
        issue(1, 1);

        for (int c = 0; c < VNCH; ++c) {
            CP_WAIT(1);
            __syncthreads();

            if (c + 2 < VNCH) issue(c + 2, (c + 2) % 3);
            else CP_COMMIT();

            const uint32_t* sAw = sm + (c % 3) * VSTAGEW;
            const float*    sA  = (const float*)sAw;
            const uint32_t* sB  = sAw + VAW;

#pragma unroll
            for (int kk = 0; kk < 4; ++kk) {
                const int ka = kk * 16 + 2 * tig;
                const int kb = kk * 8 + tig;
                uint32_t af[2][4];
#pragma unroll
                for (int mf = 0; mf < 2; ++mf) {
                    const int m = wm + mf * 16 + grp;
                    float2 a0 = *(const float2*)(sA + m * VPADA + ka);
                    float2 a1 = *(const float2*)(sA + (m + 8) * VPADA + ka);
                    float2 a2 = *(const float2*)(sA + m * VPADA + ka + 8);
                    float2 a3 = *(const float2*)(sA + (m + 8) * VPADA + ka + 8);
                    af[mf][0] = pack_f16x2(a0.x, a0.y);
                    af[mf][1] = pack_f16x2(a1.x, a1.y);
                    af[mf][2] = pack_f16x2(a2.x, a2.y);
                    af[mf][3] = pack_f16x2(a3.x, a3.y);
                }
#pragma unroll
                for (int nf = 0; nf < 16; ++nf) {
                    const int n = wn + nf * 8 + grp;
                    uint32_t bf[2];
                    bf[0] = sB[n * VPADB + kb];
                    bf[1] = sB[n * VPADB + kb + 4];
#pragma unroll
                    for (int mf = 0; mf < 2; ++mf)
                        mma_m16n8k16_f16(acc[mf][nf], af[mf], bf);
                }
            }
        }

#pragma unroll
        for (int mf = 0; mf < 2; ++mf) {
            const int mlo = m0 + wm + mf * 16 + grp;
#pragma unroll
            for (int nf = 0; nf < 16; ++nf) {
                const int col = wn + nf * 8 + 2 * tig;
                const float bx = __ldg(&bval[col]);
                const float by = __ldg(&bval[col + 1]);
                uint32_t p0 = pack_f16x2(acc[mf][nf][0] + bx, acc[mf][nf][1] + by);
                uint32_t p1 = pack_f16x2(acc[mf][nf][2] + bx, acc[mf][nf][3] + by);
                *(uint32_t*)(Cval + (size_t)mlo * DM + col) = p0;
                *(uint32_t*)(Cval + (size_t)(mlo + 8) * DM + col) = p1;
            }
        }
    } else {
        // ================= DUAL PATH =================
        const int bid = blockIdx.x - VGRID;
        const int m0  = (bid >> 1) * 64;
        const int bn0 = (bid & 1) * 160;

        const int wm = (wid & 1) * 32;
        const int wnl = (wid >> 1) * 40;

        float acc[2][5][4];
#pragma unroll
        for (int i = 0; i < 2; i++)
#pragma unroll
            for (int j = 0; j < 5; j++)
#pragma unroll
                for (int l = 0; l < 4; l++) acc[i][j][l] = 0.f;

        auto issue = [&](int c, int s) {
            const uint32_t abase  = smem_u32 + (uint32_t)(s * D2STAGEW) * 4u;
            const uint32_t bhbase = abase + (uint32_t)D2AW * 4u;
            const uint32_t blbase = bhbase + (uint32_t)D2BW * 4u;
            const int k0 = c * DBK;
#pragma unroll
            for (int it = 0; it < 2; ++it) {
                int idx = tid + it * 256;
                int row = idx >> 3, col = idx & 7;
                const float* src = Adual + (size_t)(m0 + row) * GK + k0 + col * 4;
                cp_async16(abase + (uint32_t)(row * DPADA + col * 4) * 4u, src, true);
            }
#pragma unroll
            for (int it = 0; it < 3; ++it) {
                int idx = tid + it * 256;
                if (idx < 640) {
                    int row = idx >> 2, col = idx & 3;
                    const __half* src = Whi + (size_t)(bn0 + row) * GK + k0 + col * 8;
                    cp_async16(bhbase + (uint32_t)(row * DPADB + col * 4) * 4u, src, true);
                }
            }
#pragma unroll
            for (int it = 0; it < 3; ++it) {
                int idx = tid + it * 256;
                if (idx < 640) {
                    int row = idx >> 2, col = idx & 3;
                    const __half* src = Wlo + (size_t)(bn0 + row) * GK + k0 + col * 8;
                    cp_async16(blbase + (uint32_t)(row * DPADB + col * 4) * 4u, src, true);
                }
            }
            CP_COMMIT();
        };

        issue(0, 0); issue(1, 1);

        for (int c = 0; c < 8; ++c) {
            CP_WAIT(1);
            __syncthreads();

            if (c + 2 < 8) issue(c + 2, (c + 2) % 3);
            else CP_COMMIT();

            const uint32_t* sAw = sm + (c % 3) * D2STAGEW;
            const float*    sA  = (const float*)sAw;
            const uint32_t* sBh = sAw + D2AW;
            const uint32_t* sBl = sBh + D2BW;

#pragma unroll
            for (int kk = 0; kk < 2; ++kk) {
                const int ka = kk * 16 + 2 * tig;
                const int kb = kk * 8 + tig;
                uint32_t ah[2][4], al[2][4];
#pragma unroll
                for (int mf = 0; mf < 2; ++mf) {
                    const int m = wm + mf * 16 + grp;
                    float2 a0 = *(const float2*)(sA + m * DPADA + ka);
                    float2 a1 = *(const float2*)(sA + (m + 8) * DPADA + ka);
                    float2 a2 = *(const float2*)(sA + m * DPADA + ka + 8);
                    float2 a3 = *(const float2*)(sA + (m + 8) * DPADA + ka + 8);
#pragma unroll
                    for (int q = 0; q < 4; ++q) {
                        float2 av = (q == 0) ? a0 : (q == 1) ? a1 : (q == 2) ? a2 : a3;
                        uint32_t hi = pack_f16x2(av.x, av.y);
                        float2 hf = __half22float2(*(__half2*)&hi);
                        ah[mf][q] = hi;
                        al[mf][q] = pack_f16x2(av.x - hf.x, av.y - hf.y);
                    }
                }
#pragma unroll
                for (int nf = 0; nf < 5; ++nf) {
                    const int n = wnl + nf * 8 + grp;
                    uint32_t bh[2], bl[2];
                    bh[0] = sBh[n * DPADB + kb];
                    bh[1] = sBh[n * DPADB + kb + 4];
                    bl[0] = sBl[n * DPADB + kb];
                    bl[1] = sBl[n * DPADB + kb + 4];
#pragma unroll
                    for (int mf = 0; mf < 2; ++mf) {
                        mma_m16n8k16_f16(acc[mf][nf], ah[mf], bh);
                        mma_m16n8k16_f16(acc[mf][nf], ah[mf], bl);
                        mma_m16n8k16_f16(acc[mf][nf], al[mf], bh);
                    }
                }
            }
        }

#pragma unroll
        for (int mf = 0; mf < 2; ++mf) {
            const int mlo = m0 + wm + mf * 16 + grp;
#pragma unroll
            for (int nf = 0; nf < 5; ++nf) {
                const int col = bn0 + wnl + nf * 8 + 2 * tig;
                if (col >= 288) continue;
                const float bx = __ldg(&bdual[col]);
                const float by = __ldg(&bdual[col + 1]);
                float2 v0 = make_float2(acc[mf][nf][0] + bx, acc[mf][nf][1] + by);
                float2 v1 = make_float2(acc[mf][nf][2] + bx, acc[mf][nf][3] + by);
                *(float2*)(Cdual + (size_t)mlo * 288 + col) = v0;
                *(float2*)(Cdual + (size_t)(mlo + 8) * 288 + col) = v1;
            }
        }
    }
}

// ===========================================================================
// Out-projection GEMM, N-split, BK=64: grid 150 = 75 m x 2 n-halves.
// CTA tile 64x128, 4 chunks, 3 stages (110.6 KB), warp tile 32x32.
// ===========================================================================
#define OBK     64
#define ONCH    (GK / OBK)       // 4
#define OPADA   72
#define OPADB   36
#define OAW     (64 * OPADA)     // 4608 words
#define OBW     (128 * OPADB)    // 4608 words
#define OSTAGEW (OAW + OBW)      // 9216 words = 36864 B
#define ONSTAGE 3

__global__ __launch_bounds__(256, 2) void gemm_out(
    const float* __restrict__ A, const __half* __restrict__ W,
    const float* __restrict__ bias, float* __restrict__ C, int M)
{
    extern __shared__ uint32_t sm[];

    const int tid  = threadIdx.x;
    const int wid  = tid >> 5;
    const int lane = tid & 31;
    const int grp  = lane >> 2;
    const int tig  = lane & 3;

    const int m0  = (blockIdx.x >> 1) * 64;
    const int bn0 = (blockIdx.x & 1) * 128;
    const int wm  = (wid & 1) * 32;
    const int wn  = (wid >> 1) * 32;

    const uint32_t smem_u32 = (uint32_t)__cvta_generic_to_shared(sm);

    float acc[2][4][4];
#pragma unroll
    for (int i = 0; i < 2; i++)
#pragma unroll
        for (int j = 0; j < 4; j++)
#pragma unroll
            for (int l = 0; l < 4; l++) acc[i][j][l] = 0.f;

    auto issue = [&](int c, int s) {
        const uint32_t abase = smem_u32 + (uint32_t)(s * OSTAGEW) * 4u;
        const uint32_t bbase = abase + (uint32_t)OAW * 4u;
        const int k0 = c * OBK;
        // A fp32: 64 rows x 16 = 1024 -> 4/thread
#pragma unroll
        for (int it = 0; it < 4; ++it) {
            int idx = tid + it * 256;
            int row = idx >> 4, col = idx & 15;
            bool v = (m0 + row) < M;
            const float* src = A + (size_t)(m0 + row) * GK + k0 + col * 4;
            cp_async16(abase + (uint32_t)(row * OPADA + col * 4) * 4u, src, v);
        }
        // B f16: 128 rows x 8 = 1024 -> 4/thread
#pragma unroll
        for (int it = 0; it < 4; ++it) {
            int idx = tid + it * 256;
            int row = idx >> 3, col = idx & 7;
            const __half* src = W + (size_t)(bn0 + row) * GK + k0 + col * 8;
            cp_async16(bbase + (uint32_t)(row * OPADB + col * 4) * 4u, src, true);
        }
        CP_COMMIT();
    };

    issue(0, 0);
    issue(1, 1);

    for (int c = 0; c < ONCH; ++c) {
        CP_WAIT(1);
        __syncthreads();

        if (c + 2 < ONCH) issue(c + 2, (c + 2) % ONSTAGE);
        else CP_COMMIT();

        const uint32_t* sAw = sm + (c % ONSTAGE) * OSTAGEW;
        const float*    sA  = (const float*)sAw;
        const uint32_t* sB  = sAw + OAW;

#pragma unroll
        for (int kk = 0; kk < 4; ++kk) {
            const int ka = kk * 16 + 2 * tig;
            const int kb = kk * 8 + tig;
            uint32_t af[2][4];
#pragma unroll
            for (int mf = 0; mf < 2; ++mf) {
                const int m = wm + mf * 16 + grp;
                float2 a0 = *(const float2*)(sA + m * OPADA + ka);
                float2 a1 = *(const float2*)(sA + (m + 8) * OPADA + ka);
                float2 a2 = *(const float2*)(sA + m * OPADA + ka + 8);
                float2 a3 = *(const float2*)(sA + (m + 8) * OPADA + ka + 8);
                af[mf][0] = pack_f16x2(a0.x, a0.y);
                af[mf][1] = pack_f16x2(a1.x, a1.y);
                af[mf][2] = pack_f16x2(a2.x, a2.y);
                af[mf][3] = pack_f16x2(a3.x, a3.y);
            }
#pragma unroll
            for (int nf = 0; nf < 4; ++nf) {
                const int n = wn + nf * 8 + grp;
                uint32_t bf[2];
                bf[0] = sB[n * OPADB + kb];
                bf[1] = sB[n * OPADB + kb + 4];
#pragma unroll
                for (int mf = 0; mf < 2; ++mf)
                    mma_m16n8k16_f16(acc[mf][nf], af[mf], bf);
            }
        }
    }

#pragma unroll
    for (int mf = 0; mf < 2; ++mf) {
        const int mlo = m0 + wm + mf * 16 + grp;
#pragma unroll
        for (int nf = 0; nf < 4; ++nf) {
            const int col = bn0 + wn + nf * 8 + 2 * tig;
            const float bx = __ldg(&bias[col]);
            const float by = __ldg(&bias[col + 1]);
            if (mlo < M) {
                float2 v = make_float2(acc[mf][nf][0] + bx, acc[mf][nf][1] + by);
                *(float2*)(C + (size_t)mlo * DM + col) = v;
            }
            if (mlo + 8 < M) {
                float2 v = make_float2(acc[mf][nf][2] + bx, acc[mf][nf][3] + by);
                *(float2*)(C + (size_t)(mlo + 8) * DM + col) = v;
            }
        }
    }
}

// ---------------------------------------------------------------------------
// Sampling kernel v4: warp = head; lane = (point-group pg 0..3, channel-oct
// c8 0..7). Each lane loads uint2 (4 channels, 8 B); 4 points/iter x 3 iters
// = 12 LDG.64 per lane. Reduction: shfl_xor 8 & 16; float4 writes.
// ---------------------------------------------------------------------------
__global__ __launch_bounds__(256) void msda_sample4(
    const __half* __restrict__ value,
    const float* __restrict__ oa,
    const float* __restrict__ refp,
    float* __restrict__ out)
{
    __shared__ float  s_logit[96];
    __shared__ float2 s_mxinv[8];
    __shared__ int4   s_ofs[96];
    __shared__ float4 s_wts[96];

    const int bq = blockIdx.x;
    const int b  = bq / Q_;
    const int t  = threadIdx.x;

    if (t < 96) s_logit[t] = oa[(size_t)bq * 288 + 192 + t];
    __syncthreads();

    if (t < 8) {
        float mx = -1e30f;
#pragma unroll
        for (int p = 0; p < LP_; p++) mx = fmaxf(mx, s_logit[t * LP_ + p]);
        float s = 0.f;
#pragma unroll
        for (int p = 0; p < LP_; p++) s += __expf(s_logit[t * LP_ + p] - mx);
        s_mxinv[t] = make_float2(mx, 1.f / s);
    }
    __syncthreads();

    if (t < 96) {
        const int h = t / LP_;
        const int p = t - h * LP_;
        const float2 mi = s_mxinv[h];
        const float aw = __expf(s_logit[t] - mi.x) * mi.y;

        const float rx = refp[bq * 4 + 0];
        const float ry = refp[bq * 4 + 1];
        const float rw = refp[bq * 4 + 2];
        const float rh = refp[bq * 4 + 3];

        const float ox = oa[(size_t)bq * 288 + h * 24 + 2 * p + 0];
        const float oy = oa[(size_t)bq * 288 + h * 24 + 2 * p + 1];

        const int lvl   = p >> 2;
        const int Wl    = (lvl == 0) ? 80 : (lvl == 1) ? 40 : 20;
        const int start = (lvl == 0) ? 0 : (lvl == 1) ? 6400 : 8000;

        const float gx = (rx + ox * 0.125f * rw) * (float)Wl - 0.5f;
        const float gy = (ry + oy * 0.125f * rh) * (float)Wl - 0.5f;

        const float x0f = floorf(gx), y0f = floorf(gy);
        const int x0 = (int)x0f, y0 = (int)y0f;
        const int x1 = x0 + 1,  y1 = y0 + 1;
        const float wx1 = gx - x0f, wx0 = 1.f - wx1;
        const float wy1 = gy - y0f, wy0 = 1.f - wy1;

        const bool xv0 = (x0 >= 0) & (x0 < Wl);
        const bool xv1 = (x1 >= 0) & (x1 < Wl);
        const bool yv0 = (y0 >= 0) & (y0 < Wl);
        const bool yv1 = (y1 >= 0) & (y1 < Wl);

        const int x0c = min(max(x0, 0), Wl - 1);
        const int x1c = min(max(x1, 0), Wl - 1);
        const int y0c = min(max(y0, 0), Wl - 1);
        const int y1c = min(max(y1, 0), Wl - 1);

        const int rb = b * S_ + start;
        const int r0 = rb + y0c * Wl;
        const int r1 = rb + y1c * Wl;
        const int hb = h * HD;

        int4 o;
        o.x = (r0 + x0c) * DM + hb;
        o.y = (r0 + x1c) * DM + hb;
        o.z = (r1 + x0c) * DM + hb;
        o.w = (r1 + x1c) * DM + hb;

        float4 w;
        w.x = aw * wx0 * wy0 * (float)(xv0 & yv0);
        w.y = aw * wx1 * wy0 * (float)(xv1 & yv0);
        w.z = aw * wx0 * wy1 * (float)(xv0 & yv1);
        w.w = aw * wx1 * wy1 * (float)(xv1 & yv1);

        s_ofs[t] = o;
        s_wts[t] = w;
    }
    __syncthreads();

    const int h    = t >> 5;
    const int lane = t & 31;
    const int pg   = lane >> 3;     // point group 0..3
    const int c8   = lane & 7;      // channel oct 0..7 (4 channels each)

    float4 acc = make_float4(0.f, 0.f, 0.f, 0.f);
#pragma unroll
    for (int pi = 0; pi < 3; ++pi) {
        const int idx = h * LP_ + pi * 4 + pg;
        const int4   o = s_ofs[idx];
        const float4 w = s_wts[idx];
        uint2 u0 = __ldg((const uint2*)(value + o.x) + c8);
        uint2 u1 = __ldg((const uint2*)(value + o.y) + c8);
        uint2 u2 = __ldg((const uint2*)(value + o.z) + c8);
        uint2 u3 = __ldg((const uint2*)(value + o.w) + c8);
        float2 a0 = __half22float2(*(__half2*)&u0.x);
        float2 b0 = __half22float2(*(__half2*)&u0.y);
        float2 a1 = __half22float2(*(__half2*)&u1.x);
        float2 b1 = __half22float2(*(__half2*)&u1.y);
        float2 a2 = __half22float2(*(__half2*)&u2.x);
        float2 b2 = __half22float2(*(__half2*)&u2.y);
        float2 a3 = __half22float2(*(__half2*)&u3.x);
        float2 b3 = __half22float2(*(__half2*)&u3.y);
        acc.x += w.x * a0.x + w.y * a1.x + w.z * a2.x + w.w * a3.x;
        acc.y += w.x * a0.y + w.y * a1.y + w.z * a2.y + w.w * a3.y;
        acc.z += w.x * b0.x + w.y * b1.x + w.z * b2.x + w.w * b3.x;
        acc.w += w.x * b0.y + w.y * b1.y + w.z * b2.y + w.w * b3.y;
    }
    acc.x += __shfl_xor_sync(0xffffffffu, acc.x, 8);
    acc.y += __shfl_xor_sync(0xffffffffu, acc.y, 8);
    acc.z += __shfl_xor_sync(0xffffffffu, acc.z, 8);
    acc.w += __shfl_xor_sync(0xffffffffu, acc.w, 8);
    acc.x += __shfl_xor_sync(0xffffffffu, acc.x, 16);
    acc.y += __shfl_xor_sync(0xffffffffu, acc.y, 16);
    acc.z += __shfl_xor_sync(0xffffffffu, acc.z, 16);
    acc.w += __shfl_xor_sync(0xffffffffu, acc.w, 16);
    if (pg == 0)
        *(float4*)(out + (size_t)bq * DM + h * HD + 4 * c8) = acc;
}

// ---------------------------------------------------------------------------
extern "C" void kernel_launch(void* const* d_in, const int* in_sizes, int n_in,
                              void* d_out, int out_size)
{
    const float* hs      = (const float*)d_in[0];
    const float* ehs     = (const float*)d_in[1];
    const float* refp    = (const float*)d_in[2];
    const float* w_value = (const float*)d_in[3];
    const float* b_value = (const float*)d_in[4];
    const float* w_off   = (const float*)d_in[5];
    const float* b_off   = (const float*)d_in[6];
    const float* w_attn  = (const float*)d_in[7];
    const float* b_attn  = (const float*)d_in[8];
    const float* w_out   = (const float*)d_in[9];
    const float* b_out   = (const float*)d_in[10];
    float* out = (float*)d_out;

    float  *poa, *pmsda, *pboa;
    __half *pvalh, *pwv, *pwo, *pwhi, *pwlo;
    cudaGetSymbolAddress((void**)&pvalh, g_value_h);
    cudaGetSymbolAddress((void**)&poa,   g_oa);
    cudaGetSymbolAddress((void**)&pmsda, g_msda);
    cudaGetSymbolAddress((void**)&pwv,   g_wv_h);
    cudaGetSymbolAddress((void**)&pwo,   g_wo_h);
    cudaGetSymbolAddress((void**)&pwhi,  g_woa_hi);
    cudaGetSymbolAddress((void**)&pwlo,  g_woa_lo);
    cudaGetSymbolAddress((void**)&pboa,  g_boa);

    const int smem_out = ONSTAGE * OSTAGEW * 4;    // 110592 B
    cudaFuncSetAttribute(fused_value_dual,
                         cudaFuncAttributeMaxDynamicSharedMemorySize, FUSED_SMEM);
    cudaFuncSetAttribute(gemm_out,
                         cudaFuncAttributeMaxDynamicSharedMemorySize, smem_out);

    // 0. weight prep
    prep_weights<<<832, 256>>>(w_value, w_out, w_off, b_off, w_attn, b_attn,
                               pwv, pwo, pwhi, pwlo, pboa);

    // 1. fused: value GEMM (1050 CTAs, BK=64) + offsets/attn (150 CTAs)
    fused_value_dual<<<VGRID + DGRID, 256, FUSED_SMEM>>>(
        ehs, pwv, b_value, pvalh, hs, pwhi, pwlo, pboa, poa);

    // 2. softmax + bilinear sampling + weighted sum (8B gathers)
    msda_sample4<<<BQ, 256>>>(pvalh, poa, refp, pmsda);

    // 3. out = msda @ w_out^T + b_out  (N-split, BK=64)
    gemm_out<<<DGRID, 256, smem_out>>>(pmsda, pwo, b_out, out, BQ);
}